// round 15
// baseline (speedup 1.0000x reference)
#include <cuda_runtime.h>
#include <cuda_bf16.h>
#include <math.h>
#include <stdint.h>

// Problem constants
#define CL 4
#define CDM 768
#define CDI 1536
#define CDS 16
#define CDR 48
#define CKC 4
#define CV 32000
#define CB 2
#define CS 2048
#define CBS (CB*CS)
#define CDBC 80
#define NT_LM (CV/256)       // 125 LM-head n-tiles (BN=256)
#define NCH 16
#define CSC (CS/NCH)

// ---------------- sizes ----------------
#define W_INW  ((size_t)CL*2*CDI*CDM)
#define W_XPW  ((size_t)CL*CDBC*CDI)
#define W_DTW  ((size_t)CL*CDI*CDR)
#define W_OUTW ((size_t)CL*CDM*CDI)
#define W_LM   ((size_t)CV*2*CDM)

#define A_H    ((size_t)CBS*CDM)
#define A_XZ   ((size_t)CBS*2*CDI)
#define A_XC   ((size_t)CBS*CDI)
#define A_DBC  ((size_t)CBS*CDBC)
#define A_COMB ((size_t)CBS*2*CDM)
#define A_PART ((size_t)CBS*NT_LM)
#define A_PL   ((size_t)CB*CDI*CDS*NCH)

#define F_TOTAL (2*A_H + 2*A_XZ + 2*A_XC + 2*A_DBC + 2*A_XC + 2*A_XC + A_PART + 6*A_PL + 2*CBS)
__device__ float g_arena[F_TOTAL];

#define PL_TOTAL (2*2*(W_INW+W_XPW+W_DTW+W_OUTW) + 2*W_LM \
                  + 2*2*A_H + 2*2*A_XC + 2*2*A_DBC + 2*2*A_XC + 2*A_COMB)
__device__ __nv_bfloat16 g_planes[PL_TOTAL];

// ---------------- PTX helpers ----------------
__device__ __forceinline__ uint32_t smem_u32(const void* p) {
    uint32_t a;
    asm("{ .reg .u64 t; cvta.to.shared.u64 t, %1; cvt.u32.u64 %0, t; }"
        : "=r"(a) : "l"(p));
    return a;
}

#define CP_ASYNC16(dst_u32, src_ptr, sz) \
    asm volatile("cp.async.ca.shared.global [%0], [%1], 16, %2;" \
                 :: "r"(dst_u32), "l"(src_ptr), "r"(sz))
#define CP_COMMIT() asm volatile("cp.async.commit_group;")
#define CP_WAIT(n)  asm volatile("cp.async.wait_group %0;" :: "n"(n))

__device__ __forceinline__ void mma_bf16(float* d, const uint32_t* a, const uint32_t* b) {
    asm volatile(
        "mma.sync.aligned.m16n8k16.row.col.f32.bf16.bf16.f32 "
        "{%0,%1,%2,%3}, {%4,%5,%6,%7}, {%8,%9}, {%0,%1,%2,%3};"
        : "+f"(d[0]), "+f"(d[1]), "+f"(d[2]), "+f"(d[3])
        : "r"(a[0]), "r"(a[1]), "r"(a[2]), "r"(a[3]), "r"(b[0]), "r"(b[1]));
}

__device__ __forceinline__ void bf16_split(float v, __nv_bfloat16& h, __nv_bfloat16& l) {
    h = __float2bfloat16(v);
    l = __float2bfloat16(v - __bfloat162float(h));
}

// ---------------- batched weight split ----------------
#define NSEG 9
struct SplitArgs {
    const float4* src[NSEG];
    __nv_bfloat162* h2[NSEG];
    __nv_bfloat162* l2[NSEG];
    size_t n4[NSEG];
};

__global__ void split_all_kernel(SplitArgs a)
{
    int seg = blockIdx.y;
    const float4* src = a.src[seg];
    __nv_bfloat162* h2 = a.h2[seg];
    __nv_bfloat162* l2 = a.l2[seg];
    size_t n4 = a.n4[seg];
    size_t i = (size_t)blockIdx.x * blockDim.x + threadIdx.x;
    size_t stride = (size_t)gridDim.x * blockDim.x;
    for (; i < n4; i += stride) {
        float4 v = src[i];
        __nv_bfloat16 hx, lx, hy, ly, hz, lz, hw, lw;
        bf16_split(v.x, hx, lx); bf16_split(v.y, hy, ly);
        bf16_split(v.z, hz, lz); bf16_split(v.w, hw, lw);
        __nv_bfloat162 p, q;
        p.x = hx; p.y = hy; q.x = hz; q.y = hw;
        h2[2 * i] = p; h2[2 * i + 1] = q;
        p.x = lx; p.y = ly; q.x = lz; q.y = lw;
        l2[2 * i] = p; l2[2 * i + 1] = q;
    }
}

// ---------------- tensor-core GEMM (3x-split bf16, 128x256 block, 64x64 warp tile)
#define BM 128
#define BN 256
#define BK 32              // halves per stage
#define PH 40              // pitch in halves
#define PLA (128*PH)       // A plane halves = 5120
#define PLB (256*PH)       // B plane halves = 10240
#define BUFH (2*PLA + 2*PLB)   // 30720 halves per buffer
#define GEMM_SMEM (2*BUFH*2)   // 122880 bytes

__global__ __launch_bounds__(256, 1)
void gemm_tc(const __nv_bfloat16* __restrict__ Ah, const __nv_bfloat16* __restrict__ Al, int lda,
             const __nv_bfloat16* __restrict__ Bh, const __nv_bfloat16* __restrict__ Bl,
             float* __restrict__ C,
             int M, int N, int K,
             const float* __restrict__ bias0, const float* __restrict__ bias1,
             int act, int acc,
             __nv_bfloat16* __restrict__ Ch, __nv_bfloat16* __restrict__ Cl,
             float* __restrict__ expPart,
             size_t dsA, size_t dsB, size_t dsC)
{
    extern __shared__ __nv_bfloat16 smh[];
    const uint32_t smb = smem_u32(smh);

    const size_t dirz = blockIdx.z;
    Ah += dirz * dsA; Al += dirz * dsA;
    Bh += dirz * dsB; Bl += dirz * dsB;
    C  += dirz * dsC;
    if (Ch) { Ch += dirz * dsC; Cl += dirz * dsC; }
    const float* bias = dirz ? bias1 : bias0;

    const int tid = threadIdx.x;
    const int wid = tid >> 5, lane = tid & 31;
    const int g = lane >> 2, tg = lane & 3;
    const int warp_m = (wid & 1) * 64;
    const int warp_n = (wid >> 1) * 64;
    const int m0 = blockIdx.x * BM;
    const int n0 = blockIdx.y * BN;

    float accr[4][8][4];
#pragma unroll
    for (int i = 0; i < 4; i++)
#pragma unroll
        for (int j = 0; j < 8; j++)
#pragma unroll
            for (int r = 0; r < 4; r++) accr[i][j][r] = 0.f;

    const int nIter = (K + BK - 1) / BK;

#define PREFETCH(it, bufv) do {                                                 \
    int k0p = (it) * BK;                                                        \
    _Pragma("unroll")                                                           \
    for (int j = 0; j < 12; j++) {                                              \
        int c = tid + j * 256;                                                  \
        uint32_t dst;                                                           \
        const __nv_bfloat16* src;                                               \
        int sz = 16;                                                            \
        if (c < 1024) {                                                         \
            int p = c >> 9;                                                     \
            int idx = c & 511;                                                  \
            int r = idx >> 2;                                                   \
            int kc = (idx & 3) * 8;                                             \
            dst = smb + (uint32_t)(((bufv) * BUFH + p * PLA + r * PH + kc) * 2); \
            if (k0p + kc >= K) { sz = 0; src = Ah; }                            \
            else src = (p == 0 ? Ah : Al) + (size_t)(m0 + r) * lda + k0p + kc;  \
        } else {                                                                \
            int c2 = c - 1024;                                                  \
            int p = c2 >> 10;                                                   \
            int idx = c2 & 1023;                                                \
            int r = idx >> 2;                                                   \
            int kc = (idx & 3) * 8;                                             \
            dst = smb + (uint32_t)(((bufv) * BUFH + 2 * PLA + p * PLB + r * PH + kc) * 2); \
            if (k0p + kc >= K || n0 + r >= N) { sz = 0; src = Bh; }             \
            else src = (p == 0 ? Bh : Bl) + (size_t)(n0 + r) * K + k0p + kc;    \
        }                                                                       \
        CP_ASYNC16(dst, src, sz);                                               \
    }                                                                           \
    CP_COMMIT();                                                                \
} while (0)

    PREFETCH(0, 0);

    int buf = 0;
    for (int it = 0; it < nIter; it++) {
        if (it + 1 < nIter) { PREFETCH(it + 1, buf ^ 1); CP_WAIT(1); }
        else CP_WAIT(0);
        __syncthreads();

        const uint32_t* sAh = (const uint32_t*)(smh + (size_t)buf * BUFH);
        const uint32_t* sAl = sAh + PLA / 2;
        const uint32_t* sBh = sAh + PLA;
        const uint32_t* sBl = sBh + PLB / 2;

#pragma unroll
        for (int s = 0; s < 2; s++) {
            const int kb = s * 8 + tg;   // uint32 index within row
            uint32_t ahi[4][4], alo[4][4];
#pragma unroll
            for (int mt = 0; mt < 4; mt++) {
                int r0 = (warp_m + mt * 16 + g) * (PH / 2) + kb;
                int r1 = r0 + 8 * (PH / 2);
                ahi[mt][0] = sAh[r0]; ahi[mt][1] = sAh[r1];
                ahi[mt][2] = sAh[r0 + 4]; ahi[mt][3] = sAh[r1 + 4];
                alo[mt][0] = sAl[r0]; alo[mt][1] = sAl[r1];
                alo[mt][2] = sAl[r0 + 4]; alo[mt][3] = sAl[r1 + 4];
            }
#pragma unroll
            for (int nt = 0; nt < 8; nt++) {
                int c0 = (warp_n + nt * 8 + g) * (PH / 2) + kb;
                uint32_t bh[2] = { sBh[c0], sBh[c0 + 4] };
                uint32_t bl[2] = { sBl[c0], sBl[c0 + 4] };
#pragma unroll
                for (int mt = 0; mt < 4; mt++) {
                    mma_bf16(accr[mt][nt], ahi[mt], bh);
                    mma_bf16(accr[mt][nt], ahi[mt], bl);
                    mma_bf16(accr[mt][nt], alo[mt], bh);
                }
            }
        }
        __syncthreads();
        buf ^= 1;
    }

    // epilogue
    float es[4][2];
    if (expPart) {
#pragma unroll
        for (int i = 0; i < 4; i++) { es[i][0] = 0.f; es[i][1] = 0.f; }
    }

#pragma unroll
    for (int mt = 0; mt < 4; mt++) {
        int row0 = m0 + warp_m + mt * 16 + g;
#pragma unroll
        for (int nt = 0; nt < 8; nt++) {
            int col0 = n0 + warp_n + nt * 8 + tg * 2;
#pragma unroll
            for (int half = 0; half < 2; half++) {
                int m = row0 + half * 8;
#pragma unroll
                for (int j = 0; j < 2; j++) {
                    int n = col0 + j;
                    if (n < N) {
                        float v = accr[mt][nt][half * 2 + j];
                        if (bias) v += bias[n];
                        if (act == 1) v = (v > 20.f) ? v : log1pf(expf(v));
                        size_t off = (size_t)m * N + n;
                        if (acc) v += C[off];
                        C[off] = v;
                        if (Ch) {
                            __nv_bfloat16 hh, ll;
                            bf16_split(v, hh, ll);
                            Ch[off] = hh; Cl[off] = ll;
                        }
                        if (expPart) es[mt][half] += __expf(v);
                    }
                }
            }
        }
    }

    if (expPart) {
        __syncthreads();
        float* srow = (float*)smh;
#pragma unroll
        for (int mt = 0; mt < 4; mt++)
#pragma unroll
            for (int half = 0; half < 2; half++) {
                float e = es[mt][half];
                e += __shfl_xor_sync(0xffffffffu, e, 1);
                e += __shfl_xor_sync(0xffffffffu, e, 2);
                if (tg == 0)
                    srow[(warp_m + mt * 16 + g + half * 8) * 4 + (wid >> 1)] = e;
            }
        __syncthreads();
        if (tid < 128) {
            float s = srow[tid * 4] + srow[tid * 4 + 1] + srow[tid * 4 + 2] + srow[tid * 4 + 3];
            expPart[(size_t)blockIdx.y * M + m0 + tid] = s;
        }
    }
}

// ---------------- embedding ----------------
__global__ void embed_kernel(const int* __restrict__ ids,
                             const float* __restrict__ emb0,
                             const float* __restrict__ emb1,
                             float* __restrict__ h)
{
    size_t idx = (size_t)blockIdx.x * blockDim.x + threadIdx.x;
    if (idx >= 2 * (size_t)CBS * CDM) return;
    int dir = (int)(idx / ((size_t)CBS * CDM));
    size_t rem = idx % ((size_t)CBS * CDM);
    int r = (int)(rem / CDM);
    int c = (int)(rem % CDM);
    int b = r / CS, t = r % CS;
    int tt = dir ? (CS - 1 - t) : t;
    int id = ids[b * CS + tt];
    const float* emb = dir ? emb1 : emb0;
    h[idx] = emb[(size_t)id * CDM + c];
}

// ---------------- RMSNorm -> bf16 planes ----------------
__global__ void rms_kernel(const float* __restrict__ x,
                           const float* __restrict__ w0,
                           const float* __restrict__ w1,
                           __nv_bfloat16* __restrict__ outh,
                           __nv_bfloat16* __restrict__ outl)
{
    int bx = blockIdx.x;
    int dir = bx >= CBS;
    int r = dir ? bx - CBS : bx;
    const float* w = dir ? w1 : w0;
    const float* xr = x + (size_t)dir * A_H + (size_t)r * CDM;
    __nv_bfloat16* oh = outh + (size_t)dir * A_H + (size_t)r * CDM;
    __nv_bfloat16* ol = outl + (size_t)dir * A_H + (size_t)r * CDM;
    float s = 0.f;
    for (int i = threadIdx.x; i < CDM; i += blockDim.x) { float v = xr[i]; s += v * v; }
    __shared__ float sm[8];
    __shared__ float scale_sh;
    for (int o = 16; o > 0; o >>= 1) s += __shfl_xor_sync(0xffffffffu, s, o);
    if ((threadIdx.x & 31) == 0) sm[threadIdx.x >> 5] = s;
    __syncthreads();
    if (threadIdx.x == 0) {
        float t = 0.f;
        for (int i = 0; i < 8; i++) t += sm[i];
        scale_sh = rsqrtf(t / CDM + 1e-5f);
    }
    __syncthreads();
    float sc = scale_sh;
    for (int i = threadIdx.x; i < CDM; i += blockDim.x) {
        float v = xr[i] * sc * w[i];
        __nv_bfloat16 h, l; bf16_split(v, h, l);
        oh[i] = h; ol[i] = l;
    }
}

// ---------------- causal conv (k=4) + bias + silu ----------------
__global__ void conv_kernel(const float* __restrict__ xz,
                            const float* __restrict__ cw0, const float* __restrict__ cw1,
                            const float* __restrict__ cb0, const float* __restrict__ cb1,
                            float* __restrict__ xc,
                            __nv_bfloat16* __restrict__ xch,
                            __nv_bfloat16* __restrict__ xcl)
{
    size_t idx = (size_t)blockIdx.x * blockDim.x + threadIdx.x;
    if (idx >= 2 * (size_t)CBS * CDI) return;
    int dir = (int)(idx / ((size_t)CBS * CDI));
    size_t rem = idx % ((size_t)CBS * CDI);
    int r = (int)(rem / CDI);
    int d = (int)(rem % CDI);
    int t = r % CS;
    const float* convw = dir ? cw1 : cw0;
    const float* convb = dir ? cb1 : cb0;
    const float* xzd = xz + (size_t)dir * A_XZ;
    float acc = convb[d];
#pragma unroll
    for (int k = 0; k < CKC; k++) {
        int tt = t - (CKC - 1) + k;
        if (tt >= 0)
            acc += xzd[(size_t)(r - (CKC - 1) + k) * (2 * CDI) + d] * convw[d * CKC + k];
    }
    float sg = 1.f / (1.f + expf(-acc));
    float v = acc * sg;
    xc[idx] = v;
    __nv_bfloat16 h, l; bf16_split(v, h, l);
    xch[idx] = h; xcl[idx] = l;
}

// ---------------- chunked selective scan ----------------
__global__ void scan_p1(const float* __restrict__ dt,
                        const float* __restrict__ xc,
                        const float* __restrict__ dbc,
                        const float* __restrict__ Al0, const float* __restrict__ Al1,
                        float* __restrict__ Pb, float* __restrict__ Lb)
{
    int gid = blockIdx.x * blockDim.x + threadIdx.x;
    int lane = gid & 15;
    int rest = gid >> 4;
    if (rest >= 2 * CB * CDI * NCH) return;
    int dir = rest / (CB * CDI * NCH);
    int rr = rest % (CB * CDI * NCH);
    int chunk = rr % NCH;
    int grp = rr / NCH;
    int d = grp % CDI, b = grp / CDI;
    const float* Alog_l = dir ? Al1 : Al0;
    float Aval = -expf(Alog_l[d * CDS + lane]);
    int t0 = chunk * CSC;
    const float* dtp = dt + (size_t)dir * A_XC + ((size_t)b * CS + t0) * CDI + d;
    const float* xp  = xc + (size_t)dir * A_XC + ((size_t)b * CS + t0) * CDI + d;
    const float* bp  = dbc + (size_t)dir * A_DBC + ((size_t)b * CS + t0) * CDBC + CDR + lane;
    float P = 1.f, h = 0.f;
    for (int t = 0; t < CSC; t++) {
        float dtv = dtp[(size_t)t * CDI];
        float xv  = xp[(size_t)t * CDI];
        float Bv  = bp[(size_t)t * CDBC];
        float a = __expf(dtv * Aval);
        P *= a;
        h = a * h + (dtv * xv) * Bv;
    }
    size_t off = (size_t)dir * A_PL + ((size_t)grp * NCH + chunk) * 16 + lane;
    Pb[off] = P; Lb[off] = h;
}

__global__ void scan_stitch(const float* __restrict__ Pb,
                            const float* __restrict__ Lb,
                            float* __restrict__ Hs)
{
    int gid = blockIdx.x * blockDim.x + threadIdx.x;
    if (gid >= 2 * CB * CDI * 16) return;
    int dir = gid / (CB * CDI * 16);
    int g2 = gid % (CB * CDI * 16);
    int lane = g2 & 15, grp = g2 >> 4;
    size_t base = (size_t)dir * A_PL;
    float hs = 0.f;
    for (int c = 0; c < NCH; c++) {
        size_t off = base + ((size_t)grp * NCH + c) * 16 + lane;
        Hs[off] = hs;
        hs = Pb[off] * hs + Lb[off];
    }
}

__global__ void scan_p2(const float* __restrict__ dt,
                        const float* __restrict__ xc,
                        const float* __restrict__ dbc,
                        const float* __restrict__ Al0, const float* __restrict__ Al1,
                        const float* __restrict__ Hs,
                        float* __restrict__ y)
{
    int gid = blockIdx.x * blockDim.x + threadIdx.x;
    int lane = gid & 15;
    int rest = gid >> 4;
    if (rest >= 2 * CB * CDI * NCH) return;
    int dir = rest / (CB * CDI * NCH);
    int rr = rest % (CB * CDI * NCH);
    int chunk = rr % NCH;
    int grp = rr / NCH;
    int d = grp % CDI, b = grp / CDI;
    const float* Alog_l = dir ? Al1 : Al0;
    float Aval = -expf(Alog_l[d * CDS + lane]);
    int t0 = chunk * CSC;
    const float* dtp = dt + (size_t)dir * A_XC + ((size_t)b * CS + t0) * CDI + d;
    const float* xp  = xc + (size_t)dir * A_XC + ((size_t)b * CS + t0) * CDI + d;
    const float* bp  = dbc + (size_t)dir * A_DBC + ((size_t)b * CS + t0) * CDBC + CDR + lane;
    const float* cp  = dbc + (size_t)dir * A_DBC + ((size_t)b * CS + t0) * CDBC + CDR + CDS + lane;
    float* yp        = y + (size_t)dir * A_XC + ((size_t)b * CS + t0) * CDI + d;
    float h = Hs[(size_t)dir * A_PL + ((size_t)grp * NCH + chunk) * 16 + lane];
    for (int t = 0; t < CSC; t++) {
        float dtv = dtp[(size_t)t * CDI];
        float xv  = xp[(size_t)t * CDI];
        float Bv  = bp[(size_t)t * CDBC];
        float Cv  = cp[(size_t)t * CDBC];
        float a = __expf(dtv * Aval);
        h = a * h + (dtv * xv) * Bv;
        float contrib = h * Cv;
        contrib += __shfl_xor_sync(0xffffffffu, contrib, 8);
        contrib += __shfl_xor_sync(0xffffffffu, contrib, 4);
        contrib += __shfl_xor_sync(0xffffffffu, contrib, 2);
        contrib += __shfl_xor_sync(0xffffffffu, contrib, 1);
        if (lane == 0) yp[(size_t)t * CDI] = contrib;
    }
}

// ---------------- gate -> bf16 planes ----------------
__global__ void gate_kernel(const float* __restrict__ y,
                            const float* __restrict__ xc,
                            const float* __restrict__ xz,
                            const float* __restrict__ Dp0, const float* __restrict__ Dp1,
                            __nv_bfloat16* __restrict__ gh,
                            __nv_bfloat16* __restrict__ gl)
{
    size_t idx = (size_t)blockIdx.x * blockDim.x + threadIdx.x;
    if (idx >= 2 * (size_t)CBS * CDI) return;
    int dir = (int)(idx / ((size_t)CBS * CDI));
    size_t rem = idx % ((size_t)CBS * CDI);
    int r = (int)(rem / CDI);
    int d = (int)(rem % CDI);
    const float* Dp = dir ? Dp1 : Dp0;
    float z = xz[(size_t)dir * A_XZ + (size_t)r * (2 * CDI) + CDI + d];
    float sz = z / (1.f + expf(-z));
    float v = (y[idx] + Dp[d] * xc[idx]) * sz;
    __nv_bfloat16 h, l; bf16_split(v, h, l);
    gh[idx] = h; gl[idx] = l;
}

// ---------------- final rms + concat ----------------
__global__ void combined_kernel(const float* __restrict__ hf,
                                const float* __restrict__ hb,
                                const float* __restrict__ wf,
                                const float* __restrict__ wb,
                                __nv_bfloat16* __restrict__ combh,
                                __nv_bfloat16* __restrict__ combl)
{
    int r = blockIdx.x;
    int b = r / CS, t = r % CS;
    const float* xf = hf + (size_t)r * CDM;
    const float* xb = hb + ((size_t)b * CS + (CS - 1 - t)) * CDM;
    __shared__ float sm[8];
    __shared__ float sc_sh;

    float s = 0.f;
    for (int i = threadIdx.x; i < CDM; i += blockDim.x) { float v = xf[i]; s += v * v; }
    for (int o = 16; o > 0; o >>= 1) s += __shfl_xor_sync(0xffffffffu, s, o);
    if ((threadIdx.x & 31) == 0) sm[threadIdx.x >> 5] = s;
    __syncthreads();
    if (threadIdx.x == 0) {
        float tt = 0.f; for (int i = 0; i < 8; i++) tt += sm[i];
        sc_sh = rsqrtf(tt / CDM + 1e-5f);
    }
    __syncthreads();
    float sc = sc_sh;
    for (int i = threadIdx.x; i < CDM; i += blockDim.x) {
        float v = xf[i] * sc * wf[i];
        __nv_bfloat16 h, l; bf16_split(v, h, l);
        combh[(size_t)r * (2 * CDM) + i] = h;
        combl[(size_t)r * (2 * CDM) + i] = l;
    }
    __syncthreads();

    s = 0.f;
    for (int i = threadIdx.x; i < CDM; i += blockDim.x) { float v = xb[i]; s += v * v; }
    for (int o = 16; o > 0; o >>= 1) s += __shfl_xor_sync(0xffffffffu, s, o);
    if ((threadIdx.x & 31) == 0) sm[threadIdx.x >> 5] = s;
    __syncthreads();
    if (threadIdx.x == 0) {
        float tt = 0.f; for (int i = 0; i < 8; i++) tt += sm[i];
        sc_sh = rsqrtf(tt / CDM + 1e-5f);
    }
    __syncthreads();
    sc = sc_sh;
    for (int i = threadIdx.x; i < CDM; i += blockDim.x) {
        float v = xb[i] * sc * wb[i];
        __nv_bfloat16 h, l; bf16_split(v, h, l);
        combh[(size_t)r * (2 * CDM) + CDM + i] = h;
        combl[(size_t)r * (2 * CDM) + CDM + i] = l;
    }
}

// ---------------- loss ----------------
__global__ void loss_sum_kernel(const float* __restrict__ part,
                                const float* __restrict__ logits,
                                const int* __restrict__ labels,
                                float* __restrict__ nll,
                                float* __restrict__ valid)
{
    int r = blockIdx.x * blockDim.x + threadIdx.x;
    if (r >= CBS) return;
    float S = 0.f;
    for (int i = 0; i < NT_LM; i++) S += part[(size_t)i * CBS + r];
    int lab = labels[r];
    if (lab == -100) { nll[r] = 0.f; valid[r] = 0.f; }
    else {
        nll[r] = logf(S) - logits[(size_t)r * CV + lab];
        valid[r] = 1.f;
    }
}

__global__ void loss_final_kernel(const float* __restrict__ nll,
                                  const float* __restrict__ valid,
                                  float* __restrict__ out)
{
    __shared__ float sm[8], sc[8];
    float s = 0.f, c = 0.f;
    for (int i = threadIdx.x; i < CBS; i += blockDim.x) { s += nll[i]; c += valid[i]; }
    for (int o = 16; o > 0; o >>= 1) {
        s += __shfl_xor_sync(0xffffffffu, s, o);
        c += __shfl_xor_sync(0xffffffffu, c, o);
    }
    if ((threadIdx.x & 31) == 0) { sm[threadIdx.x >> 5] = s; sc[threadIdx.x >> 5] = c; }
    __syncthreads();
    if (threadIdx.x == 0) {
        float ts = 0.f, tc = 0.f;
        for (int i = 0; i < 8; i++) { ts += sm[i]; tc += sc[i]; }
        out[0] = ts / fmaxf(tc, 1.f);
    }
}

// ---------------- host orchestration ----------------
extern "C" void kernel_launch(void* const* d_in, const int* in_sizes, int n_in,
                              void* d_out, int out_size)
{
    const int* ids    = (const int*)d_in[0];
    const int* labels = (const int*)d_in[1];
    const float* P[27];
    for (int i = 2; i < 27; i++) P[i] = (const float*)d_in[i];

    const float* emb[2]   = { P[2],  P[14] };
    const float* norm[2]  = { P[3],  P[15] };
    const float* inw[2]   = { P[4],  P[16] };
    const float* convw[2] = { P[5],  P[17] };
    const float* convb[2] = { P[6],  P[18] };
    const float* xpw[2]   = { P[7],  P[19] };
    const float* dtw[2]   = { P[8],  P[20] };
    const float* dtb[2]   = { P[9],  P[21] };
    const float* Alog[2]  = { P[10], P[22] };
    const float* Dp[2]    = { P[11], P[23] };
    const float* outw[2]  = { P[12], P[24] };
    const float* fnorm[2] = { P[13], P[25] };
    const float* lm_w     = P[26];

    static int smem_set = 0;
    if (!smem_set) {
        cudaFuncSetAttribute(gemm_tc, cudaFuncAttributeMaxDynamicSharedMemorySize, GEMM_SMEM);
        smem_set = 1;
    }

    float* arena = nullptr;
    cudaGetSymbolAddress((void**)&arena, g_arena);
    __nv_bfloat16* planes = nullptr;
    cudaGetSymbolAddress((void**)&planes, g_planes);

    size_t fo = 0;
    auto fbump = [&](size_t n) { float* p = arena + fo; fo += n; return p; };
    size_t po = 0;
    auto pbump = [&](size_t n) { __nv_bfloat16* p = planes + po; po += n; return p; };

    __nv_bfloat16* inwH  = pbump(2 * W_INW);
    __nv_bfloat16* inwL  = pbump(2 * W_INW);
    __nv_bfloat16* xpwH  = pbump(2 * W_XPW);
    __nv_bfloat16* xpwL  = pbump(2 * W_XPW);
    __nv_bfloat16* dtwH  = pbump(2 * W_DTW);
    __nv_bfloat16* dtwL  = pbump(2 * W_DTW);
    __nv_bfloat16* outwH = pbump(2 * W_OUTW);
    __nv_bfloat16* outwL = pbump(2 * W_OUTW);
    __nv_bfloat16* lmH = pbump(W_LM);
    __nv_bfloat16* lmL = pbump(W_LM);

    __nv_bfloat16* xnH  = pbump(2 * A_H);
    __nv_bfloat16* xnL  = pbump(2 * A_H);
    __nv_bfloat16* xcHp = pbump(2 * A_XC);
    __nv_bfloat16* xcLp = pbump(2 * A_XC);
    __nv_bfloat16* dbcHp = pbump(2 * A_DBC);
    __nv_bfloat16* dbcLp = pbump(2 * A_DBC);
    __nv_bfloat16* gHp = pbump(2 * A_XC);
    __nv_bfloat16* gLp = pbump(2 * A_XC);
    __nv_bfloat16* combH = pbump(A_COMB);
    __nv_bfloat16* combL = pbump(A_COMB);

    float* hB   = fbump(2 * A_H);
    float* xzB  = fbump(2 * A_XZ);
    float* xcB  = fbump(2 * A_XC);
    float* dbcB = fbump(2 * A_DBC);
    float* dtB  = fbump(2 * A_XC);
    float* yB   = fbump(2 * A_XC);
    float* part = fbump(A_PART);
    float* Pb = fbump(2 * A_PL);
    float* Lb = fbump(2 * A_PL);
    float* Hs = fbump(2 * A_PL);
    float* nllb = fbump(CBS);
    float* valb = fbump(CBS);
    float* logits = (float*)d_out;

    SplitArgs sa;
    int si = 0;
    auto addseg = [&](const float* src, __nv_bfloat16* h, __nv_bfloat16* l, size_t n) {
        sa.src[si] = (const float4*)src;
        sa.h2[si] = (__nv_bfloat162*)h;
        sa.l2[si] = (__nv_bfloat162*)l;
        sa.n4[si] = n / 4;
        si++;
    };
    for (int d = 0; d < 2; d++) {
        addseg(inw[d],  inwH + d * W_INW,   inwL + d * W_INW,   W_INW);
        addseg(xpw[d],  xpwH + d * W_XPW,   xpwL + d * W_XPW,   W_XPW);
        addseg(dtw[d],  dtwH + d * W_DTW,   dtwL + d * W_DTW,   W_DTW);
        addseg(outw[d], outwH + d * W_OUTW, outwL + d * W_OUTW, W_OUTW);
    }
    addseg(lm_w, lmH, lmL, W_LM);
    split_all_kernel<<<dim3(512, NSEG), 256>>>(sa);   // #1

    const int EL_THREADS = 256;
    int grid_hdm2 = (int)((2 * (size_t)CBS * CDM + EL_THREADS - 1) / EL_THREADS);
    int grid_hdi2 = (int)((2 * (size_t)CBS * CDI + EL_THREADS - 1) / EL_THREADS);
    int grid_scan2 = (2 * CB * CDI * NCH * 16 + 255) / 256;
    int grid_stitch2 = (2 * CB * CDI * 16 + 255) / 256;

    embed_kernel<<<grid_hdm2, EL_THREADS>>>(ids, emb[0], emb[1], hB);   // #2

    for (int l = 0; l < CL; l++) {
        size_t loI = (size_t)l * 2 * CDI * CDM;
        size_t loX = (size_t)l * CDBC * CDI;
        size_t loD = (size_t)l * CDI * CDR;
        size_t loO = (size_t)l * CDM * CDI;

        rms_kernel<<<2 * CBS, 256>>>(hB, norm[0] + (size_t)l * CDM, norm[1] + (size_t)l * CDM,
                                     xnH, xnL);                          // #3 (l=0)
        // xz = xn @ inw^T                                               // #4 (l=0) <- profiled
        gemm_tc<<<dim3(CBS / BM, (2 * CDI + BN - 1) / BN, 2), 256, GEMM_SMEM>>>(
            xnH, xnL, CDM, inwH + loI, inwL + loI,
            xzB, CBS, 2 * CDI, CDM, nullptr, nullptr, 0, 0,
            nullptr, nullptr, nullptr,
            A_H, W_INW, A_XZ);
        conv_kernel<<<grid_hdi2, EL_THREADS>>>(
            xzB, convw[0] + (size_t)l * CDI * CKC, convw[1] + (size_t)l * CDI * CKC,
            convb[0] + (size_t)l * CDI, convb[1] + (size_t)l * CDI,
            xcB, xcHp, xcLp);
        // dbc = xc @ xpw^T
        gemm_tc<<<dim3(CBS / BM, 1, 2), 256, GEMM_SMEM>>>(
            xcHp, xcLp, CDI, xpwH + loX, xpwL + loX,
            dbcB, CBS, CDBC, CDI, nullptr, nullptr, 0, 0,
            dbcHp, dbcLp, nullptr,
            A_XC, W_XPW, A_DBC);
        // dt = softplus(dbc[:, :48] @ dtw^T + dtb)
        gemm_tc<<<dim3(CBS / BM, (CDI + BN - 1) / BN, 2), 256, GEMM_SMEM>>>(
            dbcHp, dbcLp, CDBC, dtwH + loD, dtwL + loD,
            dtB, CBS, CDI, CDR,
            dtb[0] + (size_t)l * CDI, dtb[1] + (size_t)l * CDI, 1, 0,
            nullptr, nullptr, nullptr,
            A_DBC, W_DTW, A_XC);
        scan_p1<<<grid_scan2, 256>>>(dtB, xcB, dbcB,
                                     Alog[0] + (size_t)l * CDI * CDS,
                                     Alog[1] + (size_t)l * CDI * CDS, Pb, Lb);
        scan_stitch<<<grid_stitch2, 256>>>(Pb, Lb, Hs);
        scan_p2<<<grid_scan2, 256>>>(dtB, xcB, dbcB,
                                     Alog[0] + (size_t)l * CDI * CDS,
                                     Alog[1] + (size_t)l * CDI * CDS, Hs, yB);
        gate_kernel<<<grid_hdi2, EL_THREADS>>>(
            yB, xcB, xzB, Dp[0] + (size_t)l * CDI, Dp[1] + (size_t)l * CDI,
            gHp, gLp);
        // h += g @ outw^T
        gemm_tc<<<dim3(CBS / BM, (CDM + BN - 1) / BN, 2), 256, GEMM_SMEM>>>(
            gHp, gLp, CDI, outwH + loO, outwL + loO,
            hB, CBS, CDM, CDI, nullptr, nullptr, 0, 1,
            nullptr, nullptr, nullptr,
            A_XC, W_OUTW, A_H);
    }

    combined_kernel<<<CBS, 256>>>(hB, hB + A_H, fnorm[0], fnorm[1], combH, combL);

    // LM head (+ fused exp partials)
    gemm_tc<<<dim3(CBS / BM, CV / BN, 1), 256, GEMM_SMEM>>>(
        combH, combL, 2 * CDM, lmH, lmL,
        logits, CBS, CV, 2 * CDM, nullptr, nullptr, 0, 0,
        nullptr, nullptr, part,
        0, 0, 0);

    loss_sum_kernel<<<(CBS + 255) / 256, 256>>>(part, logits, labels, nllb, valb);
    loss_final_kernel<<<1, 256>>>(nllb, valb, logits + (out_size - 1));
}

// round 16
// speedup vs baseline: 1.1497x; 1.1497x over previous
#include <cuda_runtime.h>
#include <cuda_bf16.h>
#include <math.h>
#include <stdint.h>

// Problem constants
#define CL 4
#define CDM 768
#define CDI 1536
#define CDS 16
#define CDR 48
#define CKC 4
#define CV 32000
#define CB 2
#define CS 2048
#define CBS (CB*CS)
#define CDBC 80
#define NT_LM (CV/128)
#define NCH 16
#define CSC (CS/NCH)

// ---------------- sizes ----------------
#define W_INW  ((size_t)CL*2*CDI*CDM)
#define W_XPW  ((size_t)CL*CDBC*CDI)
#define W_DTW  ((size_t)CL*CDI*CDR)
#define W_OUTW ((size_t)CL*CDM*CDI)
#define W_LM   ((size_t)CV*2*CDM)

#define A_H    ((size_t)CBS*CDM)
#define A_XZ   ((size_t)CBS*2*CDI)
#define A_XC   ((size_t)CBS*CDI)
#define A_DBC  ((size_t)CBS*CDBC)
#define A_COMB ((size_t)CBS*2*CDM)
#define A_PART ((size_t)CBS*NT_LM)
#define A_PL   ((size_t)CB*CDI*CDS*NCH)

#define F_TOTAL (2*A_H + 2*A_XZ + 2*A_XC + 2*A_DBC + 2*A_XC + 2*A_XC + A_PART + 6*A_PL + 2*CBS)
__device__ float g_arena[F_TOTAL];

#define PL_TOTAL (2*2*(W_INW+W_XPW+W_DTW+W_OUTW) + 2*W_LM \
                  + 2*2*A_H + 2*2*A_XC + 2*2*A_DBC + 2*2*A_XC + 2*A_COMB)
__device__ __nv_bfloat16 g_planes[PL_TOTAL];

// ---------------- PTX helpers ----------------
__device__ __forceinline__ uint32_t smem_u32(const void* p) {
    uint32_t a;
    asm("{ .reg .u64 t; cvta.to.shared.u64 t, %1; cvt.u32.u64 %0, t; }"
        : "=r"(a) : "l"(p));
    return a;
}

#define CP_ASYNC16(dst_u32, src_ptr, sz) \
    asm volatile("cp.async.ca.shared.global [%0], [%1], 16, %2;" \
                 :: "r"(dst_u32), "l"(src_ptr), "r"(sz))
#define CP_COMMIT() asm volatile("cp.async.commit_group;")
#define CP_WAIT(n)  asm volatile("cp.async.wait_group %0;" :: "n"(n))

__device__ __forceinline__ void mma_bf16(float* d, const uint32_t* a, const uint32_t* b) {
    asm volatile(
        "mma.sync.aligned.m16n8k16.row.col.f32.bf16.bf16.f32 "
        "{%0,%1,%2,%3}, {%4,%5,%6,%7}, {%8,%9}, {%0,%1,%2,%3};"
        : "+f"(d[0]), "+f"(d[1]), "+f"(d[2]), "+f"(d[3])
        : "r"(a[0]), "r"(a[1]), "r"(a[2]), "r"(a[3]), "r"(b[0]), "r"(b[1]));
}

__device__ __forceinline__ void bf16_split(float v, __nv_bfloat16& h, __nv_bfloat16& l) {
    h = __float2bfloat16(v);
    l = __float2bfloat16(v - __bfloat162float(h));
}

// ---------------- batched weight split ----------------
#define NSEG 9
struct SplitArgs {
    const float4* src[NSEG];
    __nv_bfloat162* h2[NSEG];
    __nv_bfloat162* l2[NSEG];
    size_t n4[NSEG];
};

__global__ void split_all_kernel(SplitArgs a)
{
    int seg = blockIdx.y;
    const float4* src = a.src[seg];
    __nv_bfloat162* h2 = a.h2[seg];
    __nv_bfloat162* l2 = a.l2[seg];
    size_t n4 = a.n4[seg];
    size_t i = (size_t)blockIdx.x * blockDim.x + threadIdx.x;
    size_t stride = (size_t)gridDim.x * blockDim.x;
    for (; i < n4; i += stride) {
        float4 v = src[i];
        __nv_bfloat16 hx, lx, hy, ly, hz, lz, hw, lw;
        bf16_split(v.x, hx, lx); bf16_split(v.y, hy, ly);
        bf16_split(v.z, hz, lz); bf16_split(v.w, hw, lw);
        __nv_bfloat162 p, q;
        p.x = hx; p.y = hy; q.x = hz; q.y = hw;
        h2[2 * i] = p; h2[2 * i + 1] = q;
        p.x = lx; p.y = ly; q.x = lz; q.y = lw;
        l2[2 * i] = p; l2[2 * i + 1] = q;
    }
}

// ---------------- tensor-core GEMM (3x-split bf16, single-barrier pipeline)
#define BM 128
#define BN 128
#define BK 32              // halves per stage
#define PH 40              // pitch in halves
#define PLANEH (128*PH)    // 5120 halves per plane
#define BUFH (4*PLANEH)    // per buffer
#define GEMM_SMEM (2*BUFH*2)   // 81920 bytes

__global__ __launch_bounds__(256, 2)
void gemm_tc(const __nv_bfloat16* __restrict__ Ah, const __nv_bfloat16* __restrict__ Al, int lda,
             const __nv_bfloat16* __restrict__ Bh, const __nv_bfloat16* __restrict__ Bl,
             float* __restrict__ C,
             int M, int N, int K,
             const float* __restrict__ bias0, const float* __restrict__ bias1,
             int act, int acc,
             __nv_bfloat16* __restrict__ Ch, __nv_bfloat16* __restrict__ Cl,
             float* __restrict__ expPart,
             size_t dsA, size_t dsB, size_t dsC)
{
    extern __shared__ __nv_bfloat16 smh[];
    const uint32_t smb = smem_u32(smh);

    const size_t dirz = blockIdx.z;
    Ah += dirz * dsA; Al += dirz * dsA;
    Bh += dirz * dsB; Bl += dirz * dsB;
    C  += dirz * dsC;
    if (Ch) { Ch += dirz * dsC; Cl += dirz * dsC; }
    const float* bias = dirz ? bias1 : bias0;

    const int tid = threadIdx.x;
    const int wid = tid >> 5, lane = tid & 31;
    const int g = lane >> 2, tg = lane & 3;
    const int warp_m = (wid & 1) * 64;
    const int warp_n = (wid >> 1) * 32;
    const int m0 = blockIdx.x * BM;
    const int n0 = blockIdx.y * BN;

    float accr[4][4][4];
#pragma unroll
    for (int i = 0; i < 4; i++)
#pragma unroll
        for (int j = 0; j < 4; j++)
#pragma unroll
            for (int r = 0; r < 4; r++) accr[i][j][r] = 0.f;

    const int nIter = (K + BK - 1) / BK;

#define PREFETCH(it, bufv) do {                                                 \
    int k0p = (it) * BK;                                                        \
    _Pragma("unroll")                                                           \
    for (int j = 0; j < 8; j++) {                                               \
        int c = tid + j * 256;                                                  \
        int p = c >> 9;                                                         \
        int q = c & 511;                                                        \
        int r = q >> 2;                                                         \
        int kc = (q & 3) * 8;                                                   \
        uint32_t dst = smb + (uint32_t)((((bufv) * 4 + p) * PLANEH + r * PH + kc) * 2); \
        const __nv_bfloat16* src;                                               \
        int sz = 16;                                                            \
        if (p < 2) {                                                            \
            if (k0p + kc >= K) { sz = 0; src = Ah; }                            \
            else src = (p == 0 ? Ah : Al) + (size_t)(m0 + r) * lda + k0p + kc;  \
        } else {                                                                \
            if (k0p + kc >= K || n0 + r >= N) { sz = 0; src = Bh; }             \
            else src = (p == 2 ? Bh : Bl) + (size_t)(n0 + r) * K + k0p + kc;    \
        }                                                                       \
        CP_ASYNC16(dst, src, sz);                                               \
    }                                                                           \
    CP_COMMIT();                                                                \
} while (0)

    PREFETCH(0, 0);

    int buf = 0;
    for (int it = 0; it < nIter; it++) {
        // wait for buf's data, then one barrier: orders data visibility AND
        // guarantees all warps finished reading buf^1 last iteration, so the
        // next prefetch can safely overwrite it.
        CP_WAIT(0);
        __syncthreads();
        if (it + 1 < nIter) PREFETCH(it + 1, buf ^ 1);

        const uint32_t* sAh = (const uint32_t*)(smh + (size_t)buf * BUFH);
        const uint32_t* sAl = sAh + PLANEH / 2;
        const uint32_t* sBh = sAh + PLANEH;
        const uint32_t* sBl = sAh + 3 * (PLANEH / 2);

#pragma unroll
        for (int s = 0; s < 2; s++) {
            const int kb = s * 8 + tg;   // uint32 index within row
            uint32_t ahi[4][4], alo[4][4];
#pragma unroll
            for (int mt = 0; mt < 4; mt++) {
                int r0 = (warp_m + mt * 16 + g) * (PH / 2) + kb;
                int r1 = r0 + 8 * (PH / 2);
                ahi[mt][0] = sAh[r0]; ahi[mt][1] = sAh[r1];
                ahi[mt][2] = sAh[r0 + 4]; ahi[mt][3] = sAh[r1 + 4];
                alo[mt][0] = sAl[r0]; alo[mt][1] = sAl[r1];
                alo[mt][2] = sAl[r0 + 4]; alo[mt][3] = sAl[r1 + 4];
            }
#pragma unroll
            for (int nt = 0; nt < 4; nt++) {
                int c0 = (warp_n + nt * 8 + g) * (PH / 2) + kb;
                uint32_t bh[2] = { sBh[c0], sBh[c0 + 4] };
                uint32_t bl[2] = { sBl[c0], sBl[c0 + 4] };
#pragma unroll
                for (int mt = 0; mt < 4; mt++) {
                    mma_bf16(accr[mt][nt], ahi[mt], bh);
                    mma_bf16(accr[mt][nt], ahi[mt], bl);
                    mma_bf16(accr[mt][nt], alo[mt], bh);
                }
            }
        }
        buf ^= 1;
    }

    // epilogue
    float es[4][2];
    if (expPart) {
#pragma unroll
        for (int i = 0; i < 4; i++) { es[i][0] = 0.f; es[i][1] = 0.f; }
    }

#pragma unroll
    for (int mt = 0; mt < 4; mt++) {
        int row0 = m0 + warp_m + mt * 16 + g;
#pragma unroll
        for (int nt = 0; nt < 4; nt++) {
            int col0 = n0 + warp_n + nt * 8 + tg * 2;
#pragma unroll
            for (int half = 0; half < 2; half++) {
                int m = row0 + half * 8;
#pragma unroll
                for (int j = 0; j < 2; j++) {
                    int n = col0 + j;
                    if (n < N) {
                        float v = accr[mt][nt][half * 2 + j];
                        if (bias) v += bias[n];
                        if (act == 1) v = (v > 20.f) ? v : log1pf(expf(v));
                        size_t off = (size_t)m * N + n;
                        if (acc) v += C[off];
                        C[off] = v;
                        if (Ch) {
                            __nv_bfloat16 hh, ll;
                            bf16_split(v, hh, ll);
                            Ch[off] = hh; Cl[off] = ll;
                        }
                        if (expPart) es[mt][half] += __expf(v);
                    }
                }
            }
        }
    }

    if (expPart) {
        __syncthreads();
        float* srow = (float*)smh;
#pragma unroll
        for (int mt = 0; mt < 4; mt++)
#pragma unroll
            for (int half = 0; half < 2; half++) {
                float e = es[mt][half];
                e += __shfl_xor_sync(0xffffffffu, e, 1);
                e += __shfl_xor_sync(0xffffffffu, e, 2);
                if (tg == 0)
                    srow[(warp_m + mt * 16 + g + half * 8) * 4 + (wid >> 1)] = e;
            }
        __syncthreads();
        if (tid < 128) {
            float s = srow[tid * 4] + srow[tid * 4 + 1] + srow[tid * 4 + 2] + srow[tid * 4 + 3];
            expPart[(size_t)blockIdx.y * M + m0 + tid] = s;
        }
    }
}

// ---------------- embedding ----------------
__global__ void embed_kernel(const int* __restrict__ ids,
                             const float* __restrict__ emb0,
                             const float* __restrict__ emb1,
                             float* __restrict__ h)
{
    size_t idx = (size_t)blockIdx.x * blockDim.x + threadIdx.x;
    if (idx >= 2 * (size_t)CBS * CDM) return;
    int dir = (int)(idx / ((size_t)CBS * CDM));
    size_t rem = idx % ((size_t)CBS * CDM);
    int r = (int)(rem / CDM);
    int c = (int)(rem % CDM);
    int b = r / CS, t = r % CS;
    int tt = dir ? (CS - 1 - t) : t;
    int id = ids[b * CS + tt];
    const float* emb = dir ? emb1 : emb0;
    h[idx] = emb[(size_t)id * CDM + c];
}

// ---------------- RMSNorm -> bf16 planes ----------------
__global__ void rms_kernel(const float* __restrict__ x,
                           const float* __restrict__ w0,
                           const float* __restrict__ w1,
                           __nv_bfloat16* __restrict__ outh,
                           __nv_bfloat16* __restrict__ outl)
{
    int bx = blockIdx.x;
    int dir = bx >= CBS;
    int r = dir ? bx - CBS : bx;
    const float* w = dir ? w1 : w0;
    const float* xr = x + (size_t)dir * A_H + (size_t)r * CDM;
    __nv_bfloat16* oh = outh + (size_t)dir * A_H + (size_t)r * CDM;
    __nv_bfloat16* ol = outl + (size_t)dir * A_H + (size_t)r * CDM;
    float s = 0.f;
    for (int i = threadIdx.x; i < CDM; i += blockDim.x) { float v = xr[i]; s += v * v; }
    __shared__ float sm[8];
    __shared__ float scale_sh;
    for (int o = 16; o > 0; o >>= 1) s += __shfl_xor_sync(0xffffffffu, s, o);
    if ((threadIdx.x & 31) == 0) sm[threadIdx.x >> 5] = s;
    __syncthreads();
    if (threadIdx.x == 0) {
        float t = 0.f;
        for (int i = 0; i < 8; i++) t += sm[i];
        scale_sh = rsqrtf(t / CDM + 1e-5f);
    }
    __syncthreads();
    float sc = scale_sh;
    for (int i = threadIdx.x; i < CDM; i += blockDim.x) {
        float v = xr[i] * sc * w[i];
        __nv_bfloat16 h, l; bf16_split(v, h, l);
        oh[i] = h; ol[i] = l;
    }
}

// ---------------- causal conv (k=4) + bias + silu ----------------
__global__ void conv_kernel(const float* __restrict__ xz,
                            const float* __restrict__ cw0, const float* __restrict__ cw1,
                            const float* __restrict__ cb0, const float* __restrict__ cb1,
                            float* __restrict__ xc,
                            __nv_bfloat16* __restrict__ xch,
                            __nv_bfloat16* __restrict__ xcl)
{
    size_t idx = (size_t)blockIdx.x * blockDim.x + threadIdx.x;
    if (idx >= 2 * (size_t)CBS * CDI) return;
    int dir = (int)(idx / ((size_t)CBS * CDI));
    size_t rem = idx % ((size_t)CBS * CDI);
    int r = (int)(rem / CDI);
    int d = (int)(rem % CDI);
    int t = r % CS;
    const float* convw = dir ? cw1 : cw0;
    const float* convb = dir ? cb1 : cb0;
    const float* xzd = xz + (size_t)dir * A_XZ;
    float acc = convb[d];
#pragma unroll
    for (int k = 0; k < CKC; k++) {
        int tt = t - (CKC - 1) + k;
        if (tt >= 0)
            acc += xzd[(size_t)(r - (CKC - 1) + k) * (2 * CDI) + d] * convw[d * CKC + k];
    }
    float sg = 1.f / (1.f + expf(-acc));
    float v = acc * sg;
    xc[idx] = v;
    __nv_bfloat16 h, l; bf16_split(v, h, l);
    xch[idx] = h; xcl[idx] = l;
}

// ---------------- chunked selective scan ----------------
__global__ void scan_p1(const float* __restrict__ dt,
                        const float* __restrict__ xc,
                        const float* __restrict__ dbc,
                        const float* __restrict__ Al0, const float* __restrict__ Al1,
                        float* __restrict__ Pb, float* __restrict__ Lb)
{
    int gid = blockIdx.x * blockDim.x + threadIdx.x;
    int lane = gid & 15;
    int rest = gid >> 4;
    if (rest >= 2 * CB * CDI * NCH) return;
    int dir = rest / (CB * CDI * NCH);
    int rr = rest % (CB * CDI * NCH);
    int chunk = rr % NCH;
    int grp = rr / NCH;
    int d = grp % CDI, b = grp / CDI;
    const float* Alog_l = dir ? Al1 : Al0;
    float Aval = -expf(Alog_l[d * CDS + lane]);
    int t0 = chunk * CSC;
    const float* dtp = dt + (size_t)dir * A_XC + ((size_t)b * CS + t0) * CDI + d;
    const float* xp  = xc + (size_t)dir * A_XC + ((size_t)b * CS + t0) * CDI + d;
    const float* bp  = dbc + (size_t)dir * A_DBC + ((size_t)b * CS + t0) * CDBC + CDR + lane;
    float P = 1.f, h = 0.f;
    for (int t = 0; t < CSC; t++) {
        float dtv = dtp[(size_t)t * CDI];
        float xv  = xp[(size_t)t * CDI];
        float Bv  = bp[(size_t)t * CDBC];
        float a = __expf(dtv * Aval);
        P *= a;
        h = a * h + (dtv * xv) * Bv;
    }
    size_t off = (size_t)dir * A_PL + ((size_t)grp * NCH + chunk) * 16 + lane;
    Pb[off] = P; Lb[off] = h;
}

__global__ void scan_stitch(const float* __restrict__ Pb,
                            const float* __restrict__ Lb,
                            float* __restrict__ Hs)
{
    int gid = blockIdx.x * blockDim.x + threadIdx.x;
    if (gid >= 2 * CB * CDI * 16) return;
    int dir = gid / (CB * CDI * 16);
    int g2 = gid % (CB * CDI * 16);
    int lane = g2 & 15, grp = g2 >> 4;
    size_t base = (size_t)dir * A_PL;
    float hs = 0.f;
    for (int c = 0; c < NCH; c++) {
        size_t off = base + ((size_t)grp * NCH + c) * 16 + lane;
        Hs[off] = hs;
        hs = Pb[off] * hs + Lb[off];
    }
}

__global__ void scan_p2(const float* __restrict__ dt,
                        const float* __restrict__ xc,
                        const float* __restrict__ dbc,
                        const float* __restrict__ Al0, const float* __restrict__ Al1,
                        const float* __restrict__ Hs,
                        float* __restrict__ y)
{
    int gid = blockIdx.x * blockDim.x + threadIdx.x;
    int lane = gid & 15;
    int rest = gid >> 4;
    if (rest >= 2 * CB * CDI * NCH) return;
    int dir = rest / (CB * CDI * NCH);
    int rr = rest % (CB * CDI * NCH);
    int chunk = rr % NCH;
    int grp = rr / NCH;
    int d = grp % CDI, b = grp / CDI;
    const float* Alog_l = dir ? Al1 : Al0;
    float Aval = -expf(Alog_l[d * CDS + lane]);
    int t0 = chunk * CSC;
    const float* dtp = dt + (size_t)dir * A_XC + ((size_t)b * CS + t0) * CDI + d;
    const float* xp  = xc + (size_t)dir * A_XC + ((size_t)b * CS + t0) * CDI + d;
    const float* bp  = dbc + (size_t)dir * A_DBC + ((size_t)b * CS + t0) * CDBC + CDR + lane;
    const float* cp  = dbc + (size_t)dir * A_DBC + ((size_t)b * CS + t0) * CDBC + CDR + CDS + lane;
    float* yp        = y + (size_t)dir * A_XC + ((size_t)b * CS + t0) * CDI + d;
    float h = Hs[(size_t)dir * A_PL + ((size_t)grp * NCH + chunk) * 16 + lane];
    for (int t = 0; t < CSC; t++) {
        float dtv = dtp[(size_t)t * CDI];
        float xv  = xp[(size_t)t * CDI];
        float Bv  = bp[(size_t)t * CDBC];
        float Cv  = cp[(size_t)t * CDBC];
        float a = __expf(dtv * Aval);
        h = a * h + (dtv * xv) * Bv;
        float contrib = h * Cv;
        contrib += __shfl_xor_sync(0xffffffffu, contrib, 8);
        contrib += __shfl_xor_sync(0xffffffffu, contrib, 4);
        contrib += __shfl_xor_sync(0xffffffffu, contrib, 2);
        contrib += __shfl_xor_sync(0xffffffffu, contrib, 1);
        if (lane == 0) yp[(size_t)t * CDI] = contrib;
    }
}

// ---------------- gate -> bf16 planes ----------------
__global__ void gate_kernel(const float* __restrict__ y,
                            const float* __restrict__ xc,
                            const float* __restrict__ xz,
                            const float* __restrict__ Dp0, const float* __restrict__ Dp1,
                            __nv_bfloat16* __restrict__ gh,
                            __nv_bfloat16* __restrict__ gl)
{
    size_t idx = (size_t)blockIdx.x * blockDim.x + threadIdx.x;
    if (idx >= 2 * (size_t)CBS * CDI) return;
    int dir = (int)(idx / ((size_t)CBS * CDI));
    size_t rem = idx % ((size_t)CBS * CDI);
    int r = (int)(rem / CDI);
    int d = (int)(rem % CDI);
    const float* Dp = dir ? Dp1 : Dp0;
    float z = xz[(size_t)dir * A_XZ + (size_t)r * (2 * CDI) + CDI + d];
    float sz = z / (1.f + expf(-z));
    float v = (y[idx] + Dp[d] * xc[idx]) * sz;
    __nv_bfloat16 h, l; bf16_split(v, h, l);
    gh[idx] = h; gl[idx] = l;
}

// ---------------- final rms + concat ----------------
__global__ void combined_kernel(const float* __restrict__ hf,
                                const float* __restrict__ hb,
                                const float* __restrict__ wf,
                                const float* __restrict__ wb,
                                __nv_bfloat16* __restrict__ combh,
                                __nv_bfloat16* __restrict__ combl)
{
    int r = blockIdx.x;
    int b = r / CS, t = r % CS;
    const float* xf = hf + (size_t)r * CDM;
    const float* xb = hb + ((size_t)b * CS + (CS - 1 - t)) * CDM;
    __shared__ float sm[8];
    __shared__ float sc_sh;

    float s = 0.f;
    for (int i = threadIdx.x; i < CDM; i += blockDim.x) { float v = xf[i]; s += v * v; }
    for (int o = 16; o > 0; o >>= 1) s += __shfl_xor_sync(0xffffffffu, s, o);
    if ((threadIdx.x & 31) == 0) sm[threadIdx.x >> 5] = s;
    __syncthreads();
    if (threadIdx.x == 0) {
        float tt = 0.f; for (int i = 0; i < 8; i++) tt += sm[i];
        sc_sh = rsqrtf(tt / CDM + 1e-5f);
    }
    __syncthreads();
    float sc = sc_sh;
    for (int i = threadIdx.x; i < CDM; i += blockDim.x) {
        float v = xf[i] * sc * wf[i];
        __nv_bfloat16 h, l; bf16_split(v, h, l);
        combh[(size_t)r * (2 * CDM) + i] = h;
        combl[(size_t)r * (2 * CDM) + i] = l;
    }
    __syncthreads();

    s = 0.f;
    for (int i = threadIdx.x; i < CDM; i += blockDim.x) { float v = xb[i]; s += v * v; }
    for (int o = 16; o > 0; o >>= 1) s += __shfl_xor_sync(0xffffffffu, s, o);
    if ((threadIdx.x & 31) == 0) sm[threadIdx.x >> 5] = s;
    __syncthreads();
    if (threadIdx.x == 0) {
        float tt = 0.f; for (int i = 0; i < 8; i++) tt += sm[i];
        sc_sh = rsqrtf(tt / CDM + 1e-5f);
    }
    __syncthreads();
    sc = sc_sh;
    for (int i = threadIdx.x; i < CDM; i += blockDim.x) {
        float v = xb[i] * sc * wb[i];
        __nv_bfloat16 h, l; bf16_split(v, h, l);
        combh[(size_t)r * (2 * CDM) + CDM + i] = h;
        combl[(size_t)r * (2 * CDM) + CDM + i] = l;
    }
}

// ---------------- loss ----------------
__global__ void loss_sum_kernel(const float* __restrict__ part,
                                const float* __restrict__ logits,
                                const int* __restrict__ labels,
                                float* __restrict__ nll,
                                float* __restrict__ valid)
{
    int r = blockIdx.x * blockDim.x + threadIdx.x;
    if (r >= CBS) return;
    float S = 0.f;
    for (int i = 0; i < NT_LM; i++) S += part[(size_t)i * CBS + r];
    int lab = labels[r];
    if (lab == -100) { nll[r] = 0.f; valid[r] = 0.f; }
    else {
        nll[r] = logf(S) - logits[(size_t)r * CV + lab];
        valid[r] = 1.f;
    }
}

__global__ void loss_final_kernel(const float* __restrict__ nll,
                                  const float* __restrict__ valid,
                                  float* __restrict__ out)
{
    __shared__ float sm[8], sc[8];
    float s = 0.f, c = 0.f;
    for (int i = threadIdx.x; i < CBS; i += blockDim.x) { s += nll[i]; c += valid[i]; }
    for (int o = 16; o > 0; o >>= 1) {
        s += __shfl_xor_sync(0xffffffffu, s, o);
        c += __shfl_xor_sync(0xffffffffu, c, o);
    }
    if ((threadIdx.x & 31) == 0) { sm[threadIdx.x >> 5] = s; sc[threadIdx.x >> 5] = c; }
    __syncthreads();
    if (threadIdx.x == 0) {
        float ts = 0.f, tc = 0.f;
        for (int i = 0; i < 8; i++) { ts += sm[i]; tc += sc[i]; }
        out[0] = ts / fmaxf(tc, 1.f);
    }
}

// ---------------- host orchestration ----------------
extern "C" void kernel_launch(void* const* d_in, const int* in_sizes, int n_in,
                              void* d_out, int out_size)
{
    const int* ids    = (const int*)d_in[0];
    const int* labels = (const int*)d_in[1];
    const float* P[27];
    for (int i = 2; i < 27; i++) P[i] = (const float*)d_in[i];

    const float* emb[2]   = { P[2],  P[14] };
    const float* norm[2]  = { P[3],  P[15] };
    const float* inw[2]   = { P[4],  P[16] };
    const float* convw[2] = { P[5],  P[17] };
    const float* convb[2] = { P[6],  P[18] };
    const float* xpw[2]   = { P[7],  P[19] };
    const float* dtw[2]   = { P[8],  P[20] };
    const float* dtb[2]   = { P[9],  P[21] };
    const float* Alog[2]  = { P[10], P[22] };
    const float* Dp[2]    = { P[11], P[23] };
    const float* outw[2]  = { P[12], P[24] };
    const float* fnorm[2] = { P[13], P[25] };
    const float* lm_w     = P[26];

    static int smem_set = 0;
    if (!smem_set) {
        cudaFuncSetAttribute(gemm_tc, cudaFuncAttributeMaxDynamicSharedMemorySize, GEMM_SMEM);
        smem_set = 1;
    }

    float* arena = nullptr;
    cudaGetSymbolAddress((void**)&arena, g_arena);
    __nv_bfloat16* planes = nullptr;
    cudaGetSymbolAddress((void**)&planes, g_planes);

    size_t fo = 0;
    auto fbump = [&](size_t n) { float* p = arena + fo; fo += n; return p; };
    size_t po = 0;
    auto pbump = [&](size_t n) { __nv_bfloat16* p = planes + po; po += n; return p; };

    __nv_bfloat16* inwH  = pbump(2 * W_INW);
    __nv_bfloat16* inwL  = pbump(2 * W_INW);
    __nv_bfloat16* xpwH  = pbump(2 * W_XPW);
    __nv_bfloat16* xpwL  = pbump(2 * W_XPW);
    __nv_bfloat16* dtwH  = pbump(2 * W_DTW);
    __nv_bfloat16* dtwL  = pbump(2 * W_DTW);
    __nv_bfloat16* outwH = pbump(2 * W_OUTW);
    __nv_bfloat16* outwL = pbump(2 * W_OUTW);
    __nv_bfloat16* lmH = pbump(W_LM);
    __nv_bfloat16* lmL = pbump(W_LM);

    __nv_bfloat16* xnH  = pbump(2 * A_H);
    __nv_bfloat16* xnL  = pbump(2 * A_H);
    __nv_bfloat16* xcHp = pbump(2 * A_XC);
    __nv_bfloat16* xcLp = pbump(2 * A_XC);
    __nv_bfloat16* dbcHp = pbump(2 * A_DBC);
    __nv_bfloat16* dbcLp = pbump(2 * A_DBC);
    __nv_bfloat16* gHp = pbump(2 * A_XC);
    __nv_bfloat16* gLp = pbump(2 * A_XC);
    __nv_bfloat16* combH = pbump(A_COMB);
    __nv_bfloat16* combL = pbump(A_COMB);

    float* hB   = fbump(2 * A_H);
    float* xzB  = fbump(2 * A_XZ);
    float* xcB  = fbump(2 * A_XC);
    float* dbcB = fbump(2 * A_DBC);
    float* dtB  = fbump(2 * A_XC);
    float* yB   = fbump(2 * A_XC);
    float* part = fbump(A_PART);
    float* Pb = fbump(2 * A_PL);
    float* Lb = fbump(2 * A_PL);
    float* Hs = fbump(2 * A_PL);
    float* nllb = fbump(CBS);
    float* valb = fbump(CBS);
    float* logits = (float*)d_out;

    SplitArgs sa;
    int si = 0;
    auto addseg = [&](const float* src, __nv_bfloat16* h, __nv_bfloat16* l, size_t n) {
        sa.src[si] = (const float4*)src;
        sa.h2[si] = (__nv_bfloat162*)h;
        sa.l2[si] = (__nv_bfloat162*)l;
        sa.n4[si] = n / 4;
        si++;
    };
    for (int d = 0; d < 2; d++) {
        addseg(inw[d],  inwH + d * W_INW,   inwL + d * W_INW,   W_INW);
        addseg(xpw[d],  xpwH + d * W_XPW,   xpwL + d * W_XPW,   W_XPW);
        addseg(dtw[d],  dtwH + d * W_DTW,   dtwL + d * W_DTW,   W_DTW);
        addseg(outw[d], outwH + d * W_OUTW, outwL + d * W_OUTW, W_OUTW);
    }
    addseg(lm_w, lmH, lmL, W_LM);
    split_all_kernel<<<dim3(512, NSEG), 256>>>(sa);   // #1

    const int EL_THREADS = 256;
    int grid_hdm2 = (int)((2 * (size_t)CBS * CDM + EL_THREADS - 1) / EL_THREADS);
    int grid_hdi2 = (int)((2 * (size_t)CBS * CDI + EL_THREADS - 1) / EL_THREADS);
    int grid_scan2 = (2 * CB * CDI * NCH * 16 + 255) / 256;
    int grid_stitch2 = (2 * CB * CDI * 16 + 255) / 256;

    embed_kernel<<<grid_hdm2, EL_THREADS>>>(ids, emb[0], emb[1], hB);   // #2

    for (int l = 0; l < CL; l++) {
        size_t loI = (size_t)l * 2 * CDI * CDM;
        size_t loX = (size_t)l * CDBC * CDI;
        size_t loD = (size_t)l * CDI * CDR;
        size_t loO = (size_t)l * CDM * CDI;

        rms_kernel<<<2 * CBS, 256>>>(hB, norm[0] + (size_t)l * CDM, norm[1] + (size_t)l * CDM,
                                     xnH, xnL);                          // #3 (l=0)
        // xz = xn @ inw^T                                               // #4 (l=0) <- profiled
        gemm_tc<<<dim3(CBS / BM, (2 * CDI) / BN, 2), 256, GEMM_SMEM>>>(
            xnH, xnL, CDM, inwH + loI, inwL + loI,
            xzB, CBS, 2 * CDI, CDM, nullptr, nullptr, 0, 0,
            nullptr, nullptr, nullptr,
            A_H, W_INW, A_XZ);
        conv_kernel<<<grid_hdi2, EL_THREADS>>>(
            xzB, convw[0] + (size_t)l * CDI * CKC, convw[1] + (size_t)l * CDI * CKC,
            convb[0] + (size_t)l * CDI, convb[1] + (size_t)l * CDI,
            xcB, xcHp, xcLp);
        // dbc = xc @ xpw^T
        gemm_tc<<<dim3(CBS / BM, 1, 2), 256, GEMM_SMEM>>>(
            xcHp, xcLp, CDI, xpwH + loX, xpwL + loX,
            dbcB, CBS, CDBC, CDI, nullptr, nullptr, 0, 0,
            dbcHp, dbcLp, nullptr,
            A_XC, W_XPW, A_DBC);
        // dt = softplus(dbc[:, :48] @ dtw^T + dtb)
        gemm_tc<<<dim3(CBS / BM, CDI / BN, 2), 256, GEMM_SMEM>>>(
            dbcHp, dbcLp, CDBC, dtwH + loD, dtwL + loD,
            dtB, CBS, CDI, CDR,
            dtb[0] + (size_t)l * CDI, dtb[1] + (size_t)l * CDI, 1, 0,
            nullptr, nullptr, nullptr,
            A_DBC, W_DTW, A_XC);
        scan_p1<<<grid_scan2, 256>>>(dtB, xcB, dbcB,
                                     Alog[0] + (size_t)l * CDI * CDS,
                                     Alog[1] + (size_t)l * CDI * CDS, Pb, Lb);
        scan_stitch<<<grid_stitch2, 256>>>(Pb, Lb, Hs);
        scan_p2<<<grid_scan2, 256>>>(dtB, xcB, dbcB,
                                     Alog[0] + (size_t)l * CDI * CDS,
                                     Alog[1] + (size_t)l * CDI * CDS, Hs, yB);
        gate_kernel<<<grid_hdi2, EL_THREADS>>>(
            yB, xcB, xzB, Dp[0] + (size_t)l * CDI, Dp[1] + (size_t)l * CDI,
            gHp, gLp);
        // h += g @ outw^T
        gemm_tc<<<dim3(CBS / BM, CDM / BN, 2), 256, GEMM_SMEM>>>(
            gHp, gLp, CDI, outwH + loO, outwL + loO,
            hB, CBS, CDM, CDI, nullptr, nullptr, 0, 1,
            nullptr, nullptr, nullptr,
            A_XC, W_OUTW, A_H);
    }

    combined_kernel<<<CBS, 256>>>(hB, hB + A_H, fnorm[0], fnorm[1], combH, combL);

    // LM head (+ fused exp partials)
    gemm_tc<<<dim3(CBS / BM, CV / BN, 1), 256, GEMM_SMEM>>>(
        combH, combL, 2 * CDM, lmH, lmL,
        logits, CBS, CV, 2 * CDM, nullptr, nullptr, 0, 0,
        nullptr, nullptr, part,
        0, 0, 0);

    loss_sum_kernel<<<(CBS + 255) / 256, 256>>>(part, logits, labels, nllb, valb);
    loss_final_kernel<<<1, 256>>>(nllb, valb, logits + (out_size - 1));
}

// round 17
// speedup vs baseline: 1.4085x; 1.2250x over previous
#include <cuda_runtime.h>
#include <cuda_fp16.h>
#include <math.h>
#include <stdint.h>

// Problem constants
#define CL 4
#define CDM 768
#define CDI 1536
#define CDS 16
#define CDR 48
#define CKC 4
#define CV 32000
#define CB 2
#define CS 2048
#define CBS (CB*CS)
#define CDBC 80
#define NT_LM (CV/128)
#define NCH 16
#define CSC (CS/NCH)

// ---------------- sizes ----------------
#define W_INW  ((size_t)CL*2*CDI*CDM)
#define W_XPW  ((size_t)CL*CDBC*CDI)
#define W_DTW  ((size_t)CL*CDI*CDR)
#define W_OUTW ((size_t)CL*CDM*CDI)
#define W_LM   ((size_t)CV*2*CDM)

#define A_H    ((size_t)CBS*CDM)
#define A_XZ   ((size_t)CBS*2*CDI)
#define A_XC   ((size_t)CBS*CDI)
#define A_DBC  ((size_t)CBS*CDBC)
#define A_COMB ((size_t)CBS*2*CDM)
#define A_PART ((size_t)CBS*NT_LM)
#define A_PL   ((size_t)CB*CDI*CDS*NCH)

#define F_TOTAL (2*A_H + 2*A_XZ + 2*A_XC + 2*A_DBC + 2*A_XC + 2*A_XC + A_PART + 6*A_PL + 2*CBS)
__device__ float g_arena[F_TOTAL];

// fp16 plane arena: weight hi planes + activation hi/lo planes
#define PL_TOTAL (2*(W_INW+W_XPW+W_DTW+W_OUTW) + W_LM \
                  + 2*2*A_H + 2*2*A_XC + 2*2*A_DBC + 2*2*A_XC + 2*A_COMB)
__device__ __half g_planes[PL_TOTAL];

// ---------------- PTX helpers ----------------
__device__ __forceinline__ uint32_t smem_u32(const void* p) {
    uint32_t a;
    asm("{ .reg .u64 t; cvta.to.shared.u64 t, %1; cvt.u32.u64 %0, t; }"
        : "=r"(a) : "l"(p));
    return a;
}

#define CP_ASYNC16(dst_u32, src_ptr, sz) \
    asm volatile("cp.async.ca.shared.global [%0], [%1], 16, %2;" \
                 :: "r"(dst_u32), "l"(src_ptr), "r"(sz))
#define CP_COMMIT() asm volatile("cp.async.commit_group;")
#define CP_WAIT(n)  asm volatile("cp.async.wait_group %0;" :: "n"(n))

__device__ __forceinline__ void mma_f16(float* d, const uint32_t* a, const uint32_t* b) {
    asm volatile(
        "mma.sync.aligned.m16n8k16.row.col.f32.f16.f16.f32 "
        "{%0,%1,%2,%3}, {%4,%5,%6,%7}, {%8,%9}, {%0,%1,%2,%3};"
        : "+f"(d[0]), "+f"(d[1]), "+f"(d[2]), "+f"(d[3])
        : "r"(a[0]), "r"(a[1]), "r"(a[2]), "r"(a[3]), "r"(b[0]), "r"(b[1]));
}

__device__ __forceinline__ void fp16_split(float v, __half& h, __half& l) {
    h = __float2half(v);
    l = __float2half(v - __half2float(h));
}

// ---------------- batched weight split (hi plane only for weights) ----------------
#define NSEG 9
struct SplitArgs {
    const float4* src[NSEG];
    __half2* h2[NSEG];
    size_t n4[NSEG];
};

__global__ void split_all_kernel(SplitArgs a)
{
    int seg = blockIdx.y;
    const float4* src = a.src[seg];
    __half2* h2 = a.h2[seg];
    size_t n4 = a.n4[seg];
    size_t i = (size_t)blockIdx.x * blockDim.x + threadIdx.x;
    size_t stride = (size_t)gridDim.x * blockDim.x;
    for (; i < n4; i += stride) {
        float4 v = src[i];
        __half2 p, q;
        p.x = __float2half(v.x); p.y = __float2half(v.y);
        q.x = __float2half(v.z); q.y = __float2half(v.w);
        h2[2 * i] = p; h2[2 * i + 1] = q;
    }
}

// ---------------- tensor-core GEMM (fp16 2-term: a split hi/lo, b single)
// C[M,N] (+)= (Ah+Al)[M,K(lda)] * B[N,K]^T
#define BM 128
#define BN 128
#define BK 32              // halves per stage
#define PH 40              // pitch in halves
#define PLANEH (128*PH)    // 5120 halves per plane
#define BUFH (3*PLANEH)    // 3 planes per buffer (Ah, Al, B)
#define GEMM_SMEM (2*BUFH*2)   // 61440 bytes

__global__ __launch_bounds__(256, 2)
void gemm_tc(const __half* __restrict__ Ah, const __half* __restrict__ Al, int lda,
             const __half* __restrict__ Bw,
             float* __restrict__ C,
             int M, int N, int K,
             const float* __restrict__ bias0, const float* __restrict__ bias1,
             int act, int acc,
             __half* __restrict__ Ch, __half* __restrict__ Cl,
             float* __restrict__ expPart,
             size_t dsA, size_t dsB, size_t dsC)
{
    extern __shared__ __half smh[];
    const uint32_t smb = smem_u32(smh);

    const size_t dirz = blockIdx.z;
    Ah += dirz * dsA; Al += dirz * dsA;
    Bw += dirz * dsB;
    C  += dirz * dsC;
    if (Ch) { Ch += dirz * dsC; Cl += dirz * dsC; }
    const float* bias = dirz ? bias1 : bias0;

    const int tid = threadIdx.x;
    const int wid = tid >> 5, lane = tid & 31;
    const int g = lane >> 2, tg = lane & 3;
    const int warp_m = (wid & 1) * 64;
    const int warp_n = (wid >> 1) * 32;
    const int m0 = blockIdx.x * BM;
    const int n0 = blockIdx.y * BN;

    float accr[4][4][4];
#pragma unroll
    for (int i = 0; i < 4; i++)
#pragma unroll
        for (int j = 0; j < 4; j++)
#pragma unroll
            for (int r = 0; r < 4; r++) accr[i][j][r] = 0.f;

    const int nIter = (K + BK - 1) / BK;

#define PREFETCH(it, bufv) do {                                                 \
    int k0p = (it) * BK;                                                        \
    _Pragma("unroll")                                                           \
    for (int j = 0; j < 6; j++) {                                               \
        int c = tid + j * 256;                                                  \
        int p = c >> 9;                                                         \
        int q = c & 511;                                                        \
        int r = q >> 2;                                                         \
        int kc = (q & 3) * 8;                                                   \
        uint32_t dst = smb + (uint32_t)((((bufv) * 3 + p) * PLANEH + r * PH + kc) * 2); \
        const __half* src;                                                      \
        int sz = 16;                                                            \
        if (p < 2) {                                                            \
            if (k0p + kc >= K) { sz = 0; src = Ah; }                            \
            else src = (p == 0 ? Ah : Al) + (size_t)(m0 + r) * lda + k0p + kc;  \
        } else {                                                                \
            if (k0p + kc >= K || n0 + r >= N) { sz = 0; src = Bw; }             \
            else src = Bw + (size_t)(n0 + r) * K + k0p + kc;                    \
        }                                                                       \
        CP_ASYNC16(dst, src, sz);                                               \
    }                                                                           \
    CP_COMMIT();                                                                \
} while (0)

    PREFETCH(0, 0);

    int buf = 0;
    for (int it = 0; it < nIter; it++) {
        // wait for buf's data; one barrier both publishes it and retires buf^1 reads
        CP_WAIT(0);
        __syncthreads();
        if (it + 1 < nIter) PREFETCH(it + 1, buf ^ 1);

        const uint32_t* sAh = (const uint32_t*)(smh + (size_t)buf * BUFH);
        const uint32_t* sAl = sAh + PLANEH / 2;
        const uint32_t* sBw = sAh + PLANEH;

#pragma unroll
        for (int s = 0; s < 2; s++) {
            const int kb = s * 8 + tg;   // uint32 index within row
            uint32_t ahi[4][4], alo[4][4];
#pragma unroll
            for (int mt = 0; mt < 4; mt++) {
                int r0 = (warp_m + mt * 16 + g) * (PH / 2) + kb;
                int r1 = r0 + 8 * (PH / 2);
                ahi[mt][0] = sAh[r0]; ahi[mt][1] = sAh[r1];
                ahi[mt][2] = sAh[r0 + 4]; ahi[mt][3] = sAh[r1 + 4];
                alo[mt][0] = sAl[r0]; alo[mt][1] = sAl[r1];
                alo[mt][2] = sAl[r0 + 4]; alo[mt][3] = sAl[r1 + 4];
            }
#pragma unroll
            for (int nt = 0; nt < 4; nt++) {
                int c0 = (warp_n + nt * 8 + g) * (PH / 2) + kb;
                uint32_t bw[2] = { sBw[c0], sBw[c0 + 4] };
#pragma unroll
                for (int mt = 0; mt < 4; mt++) {
                    mma_f16(accr[mt][nt], ahi[mt], bw);
                    mma_f16(accr[mt][nt], alo[mt], bw);
                }
            }
        }
        buf ^= 1;
    }

    // epilogue
    float es[4][2];
    if (expPart) {
#pragma unroll
        for (int i = 0; i < 4; i++) { es[i][0] = 0.f; es[i][1] = 0.f; }
    }

#pragma unroll
    for (int mt = 0; mt < 4; mt++) {
        int row0 = m0 + warp_m + mt * 16 + g;
#pragma unroll
        for (int nt = 0; nt < 4; nt++) {
            int col0 = n0 + warp_n + nt * 8 + tg * 2;
#pragma unroll
            for (int half = 0; half < 2; half++) {
                int m = row0 + half * 8;
#pragma unroll
                for (int j = 0; j < 2; j++) {
                    int n = col0 + j;
                    if (n < N) {
                        float v = accr[mt][nt][half * 2 + j];
                        if (bias) v += bias[n];
                        if (act == 1) v = (v > 20.f) ? v : log1pf(expf(v));
                        size_t off = (size_t)m * N + n;
                        if (acc) v += C[off];
                        C[off] = v;
                        if (Ch) {
                            __half hh, ll;
                            fp16_split(v, hh, ll);
                            Ch[off] = hh; Cl[off] = ll;
                        }
                        if (expPart) es[mt][half] += __expf(v);
                    }
                }
            }
        }
    }

    if (expPart) {
        __syncthreads();
        float* srow = (float*)smh;
#pragma unroll
        for (int mt = 0; mt < 4; mt++)
#pragma unroll
            for (int half = 0; half < 2; half++) {
                float e = es[mt][half];
                e += __shfl_xor_sync(0xffffffffu, e, 1);
                e += __shfl_xor_sync(0xffffffffu, e, 2);
                if (tg == 0)
                    srow[(warp_m + mt * 16 + g + half * 8) * 4 + (wid >> 1)] = e;
            }
        __syncthreads();
        if (tid < 128) {
            float s = srow[tid * 4] + srow[tid * 4 + 1] + srow[tid * 4 + 2] + srow[tid * 4 + 3];
            expPart[(size_t)blockIdx.y * M + m0 + tid] = s;
        }
    }
}

// ---------------- embedding ----------------
__global__ void embed_kernel(const int* __restrict__ ids,
                             const float* __restrict__ emb0,
                             const float* __restrict__ emb1,
                             float* __restrict__ h)
{
    size_t idx = (size_t)blockIdx.x * blockDim.x + threadIdx.x;
    if (idx >= 2 * (size_t)CBS * CDM) return;
    int dir = (int)(idx / ((size_t)CBS * CDM));
    size_t rem = idx % ((size_t)CBS * CDM);
    int r = (int)(rem / CDM);
    int c = (int)(rem % CDM);
    int b = r / CS, t = r % CS;
    int tt = dir ? (CS - 1 - t) : t;
    int id = ids[b * CS + tt];
    const float* emb = dir ? emb1 : emb0;
    h[idx] = emb[(size_t)id * CDM + c];
}

// ---------------- RMSNorm -> fp16 planes ----------------
__global__ void rms_kernel(const float* __restrict__ x,
                           const float* __restrict__ w0,
                           const float* __restrict__ w1,
                           __half* __restrict__ outh,
                           __half* __restrict__ outl)
{
    int bx = blockIdx.x;
    int dir = bx >= CBS;
    int r = dir ? bx - CBS : bx;
    const float* w = dir ? w1 : w0;
    const float* xr = x + (size_t)dir * A_H + (size_t)r * CDM;
    __half* oh = outh + (size_t)dir * A_H + (size_t)r * CDM;
    __half* ol = outl + (size_t)dir * A_H + (size_t)r * CDM;
    float s = 0.f;
    for (int i = threadIdx.x; i < CDM; i += blockDim.x) { float v = xr[i]; s += v * v; }
    __shared__ float sm[8];
    __shared__ float scale_sh;
    for (int o = 16; o > 0; o >>= 1) s += __shfl_xor_sync(0xffffffffu, s, o);
    if ((threadIdx.x & 31) == 0) sm[threadIdx.x >> 5] = s;
    __syncthreads();
    if (threadIdx.x == 0) {
        float t = 0.f;
        for (int i = 0; i < 8; i++) t += sm[i];
        scale_sh = rsqrtf(t / CDM + 1e-5f);
    }
    __syncthreads();
    float sc = scale_sh;
    for (int i = threadIdx.x; i < CDM; i += blockDim.x) {
        float v = xr[i] * sc * w[i];
        __half h, l; fp16_split(v, h, l);
        oh[i] = h; ol[i] = l;
    }
}

// ---------------- causal conv (k=4) + bias + silu ----------------
__global__ void conv_kernel(const float* __restrict__ xz,
                            const float* __restrict__ cw0, const float* __restrict__ cw1,
                            const float* __restrict__ cb0, const float* __restrict__ cb1,
                            float* __restrict__ xc,
                            __half* __restrict__ xch,
                            __half* __restrict__ xcl)
{
    size_t idx = (size_t)blockIdx.x * blockDim.x + threadIdx.x;
    if (idx >= 2 * (size_t)CBS * CDI) return;
    int dir = (int)(idx / ((size_t)CBS * CDI));
    size_t rem = idx % ((size_t)CBS * CDI);
    int r = (int)(rem / CDI);
    int d = (int)(rem % CDI);
    int t = r % CS;
    const float* convw = dir ? cw1 : cw0;
    const float* convb = dir ? cb1 : cb0;
    const float* xzd = xz + (size_t)dir * A_XZ;
    float acc = convb[d];
#pragma unroll
    for (int k = 0; k < CKC; k++) {
        int tt = t - (CKC - 1) + k;
        if (tt >= 0)
            acc += xzd[(size_t)(r - (CKC - 1) + k) * (2 * CDI) + d] * convw[d * CKC + k];
    }
    float sg = 1.f / (1.f + expf(-acc));
    float v = acc * sg;
    xc[idx] = v;
    __half h, l; fp16_split(v, h, l);
    xch[idx] = h; xcl[idx] = l;
}

// ---------------- chunked selective scan ----------------
__global__ void scan_p1(const float* __restrict__ dt,
                        const float* __restrict__ xc,
                        const float* __restrict__ dbc,
                        const float* __restrict__ Al0, const float* __restrict__ Al1,
                        float* __restrict__ Pb, float* __restrict__ Lb)
{
    int gid = blockIdx.x * blockDim.x + threadIdx.x;
    int lane = gid & 15;
    int rest = gid >> 4;
    if (rest >= 2 * CB * CDI * NCH) return;
    int dir = rest / (CB * CDI * NCH);
    int rr = rest % (CB * CDI * NCH);
    int chunk = rr % NCH;
    int grp = rr / NCH;
    int d = grp % CDI, b = grp / CDI;
    const float* Alog_l = dir ? Al1 : Al0;
    float Aval = -expf(Alog_l[d * CDS + lane]);
    int t0 = chunk * CSC;
    const float* dtp = dt + (size_t)dir * A_XC + ((size_t)b * CS + t0) * CDI + d;
    const float* xp  = xc + (size_t)dir * A_XC + ((size_t)b * CS + t0) * CDI + d;
    const float* bp  = dbc + (size_t)dir * A_DBC + ((size_t)b * CS + t0) * CDBC + CDR + lane;
    float P = 1.f, h = 0.f;
    for (int t = 0; t < CSC; t++) {
        float dtv = dtp[(size_t)t * CDI];
        float xv  = xp[(size_t)t * CDI];
        float Bv  = bp[(size_t)t * CDBC];
        float a = __expf(dtv * Aval);
        P *= a;
        h = a * h + (dtv * xv) * Bv;
    }
    size_t off = (size_t)dir * A_PL + ((size_t)grp * NCH + chunk) * 16 + lane;
    Pb[off] = P; Lb[off] = h;
}

__global__ void scan_stitch(const float* __restrict__ Pb,
                            const float* __restrict__ Lb,
                            float* __restrict__ Hs)
{
    int gid = blockIdx.x * blockDim.x + threadIdx.x;
    if (gid >= 2 * CB * CDI * 16) return;
    int dir = gid / (CB * CDI * 16);
    int g2 = gid % (CB * CDI * 16);
    int lane = g2 & 15, grp = g2 >> 4;
    size_t base = (size_t)dir * A_PL;
    float hs = 0.f;
    for (int c = 0; c < NCH; c++) {
        size_t off = base + ((size_t)grp * NCH + c) * 16 + lane;
        Hs[off] = hs;
        hs = Pb[off] * hs + Lb[off];
    }
}

__global__ void scan_p2(const float* __restrict__ dt,
                        const float* __restrict__ xc,
                        const float* __restrict__ dbc,
                        const float* __restrict__ Al0, const float* __restrict__ Al1,
                        const float* __restrict__ Hs,
                        float* __restrict__ y)
{
    int gid = blockIdx.x * blockDim.x + threadIdx.x;
    int lane = gid & 15;
    int rest = gid >> 4;
    if (rest >= 2 * CB * CDI * NCH) return;
    int dir = rest / (CB * CDI * NCH);
    int rr = rest % (CB * CDI * NCH);
    int chunk = rr % NCH;
    int grp = rr / NCH;
    int d = grp % CDI, b = grp / CDI;
    const float* Alog_l = dir ? Al1 : Al0;
    float Aval = -expf(Alog_l[d * CDS + lane]);
    int t0 = chunk * CSC;
    const float* dtp = dt + (size_t)dir * A_XC + ((size_t)b * CS + t0) * CDI + d;
    const float* xp  = xc + (size_t)dir * A_XC + ((size_t)b * CS + t0) * CDI + d;
    const float* bp  = dbc + (size_t)dir * A_DBC + ((size_t)b * CS + t0) * CDBC + CDR + lane;
    const float* cp  = dbc + (size_t)dir * A_DBC + ((size_t)b * CS + t0) * CDBC + CDR + CDS + lane;
    float* yp        = y + (size_t)dir * A_XC + ((size_t)b * CS + t0) * CDI + d;
    float h = Hs[(size_t)dir * A_PL + ((size_t)grp * NCH + chunk) * 16 + lane];
    for (int t = 0; t < CSC; t++) {
        float dtv = dtp[(size_t)t * CDI];
        float xv  = xp[(size_t)t * CDI];
        float Bv  = bp[(size_t)t * CDBC];
        float Cv  = cp[(size_t)t * CDBC];
        float a = __expf(dtv * Aval);
        h = a * h + (dtv * xv) * Bv;
        float contrib = h * Cv;
        contrib += __shfl_xor_sync(0xffffffffu, contrib, 8);
        contrib += __shfl_xor_sync(0xffffffffu, contrib, 4);
        contrib += __shfl_xor_sync(0xffffffffu, contrib, 2);
        contrib += __shfl_xor_sync(0xffffffffu, contrib, 1);
        if (lane == 0) yp[(size_t)t * CDI] = contrib;
    }
}

// ---------------- gate -> fp16 planes ----------------
__global__ void gate_kernel(const float* __restrict__ y,
                            const float* __restrict__ xc,
                            const float* __restrict__ xz,
                            const float* __restrict__ Dp0, const float* __restrict__ Dp1,
                            __half* __restrict__ gh,
                            __half* __restrict__ gl)
{
    size_t idx = (size_t)blockIdx.x * blockDim.x + threadIdx.x;
    if (idx >= 2 * (size_t)CBS * CDI) return;
    int dir = (int)(idx / ((size_t)CBS * CDI));
    size_t rem = idx % ((size_t)CBS * CDI);
    int r = (int)(rem / CDI);
    int d = (int)(rem % CDI);
    const float* Dp = dir ? Dp1 : Dp0;
    float z = xz[(size_t)dir * A_XZ + (size_t)r * (2 * CDI) + CDI + d];
    float sz = z / (1.f + expf(-z));
    float v = (y[idx] + Dp[d] * xc[idx]) * sz;
    __half h, l; fp16_split(v, h, l);
    gh[idx] = h; gl[idx] = l;
}

// ---------------- final rms + concat ----------------
__global__ void combined_kernel(const float* __restrict__ hf,
                                const float* __restrict__ hb,
                                const float* __restrict__ wf,
                                const float* __restrict__ wb,
                                __half* __restrict__ combh,
                                __half* __restrict__ combl)
{
    int r = blockIdx.x;
    int b = r / CS, t = r % CS;
    const float* xf = hf + (size_t)r * CDM;
    const float* xb = hb + ((size_t)b * CS + (CS - 1 - t)) * CDM;
    __shared__ float sm[8];
    __shared__ float sc_sh;

    float s = 0.f;
    for (int i = threadIdx.x; i < CDM; i += blockDim.x) { float v = xf[i]; s += v * v; }
    for (int o = 16; o > 0; o >>= 1) s += __shfl_xor_sync(0xffffffffu, s, o);
    if ((threadIdx.x & 31) == 0) sm[threadIdx.x >> 5] = s;
    __syncthreads();
    if (threadIdx.x == 0) {
        float tt = 0.f; for (int i = 0; i < 8; i++) tt += sm[i];
        sc_sh = rsqrtf(tt / CDM + 1e-5f);
    }
    __syncthreads();
    float sc = sc_sh;
    for (int i = threadIdx.x; i < CDM; i += blockDim.x) {
        float v = xf[i] * sc * wf[i];
        __half h, l; fp16_split(v, h, l);
        combh[(size_t)r * (2 * CDM) + i] = h;
        combl[(size_t)r * (2 * CDM) + i] = l;
    }
    __syncthreads();

    s = 0.f;
    for (int i = threadIdx.x; i < CDM; i += blockDim.x) { float v = xb[i]; s += v * v; }
    for (int o = 16; o > 0; o >>= 1) s += __shfl_xor_sync(0xffffffffu, s, o);
    if ((threadIdx.x & 31) == 0) sm[threadIdx.x >> 5] = s;
    __syncthreads();
    if (threadIdx.x == 0) {
        float tt = 0.f; for (int i = 0; i < 8; i++) tt += sm[i];
        sc_sh = rsqrtf(tt / CDM + 1e-5f);
    }
    __syncthreads();
    sc = sc_sh;
    for (int i = threadIdx.x; i < CDM; i += blockDim.x) {
        float v = xb[i] * sc * wb[i];
        __half h, l; fp16_split(v, h, l);
        combh[(size_t)r * (2 * CDM) + CDM + i] = h;
        combl[(size_t)r * (2 * CDM) + CDM + i] = l;
    }
}

// ---------------- loss ----------------
__global__ void loss_sum_kernel(const float* __restrict__ part,
                                const float* __restrict__ logits,
                                const int* __restrict__ labels,
                                float* __restrict__ nll,
                                float* __restrict__ valid)
{
    int r = blockIdx.x * blockDim.x + threadIdx.x;
    if (r >= CBS) return;
    float S = 0.f;
    for (int i = 0; i < NT_LM; i++) S += part[(size_t)i * CBS + r];
    int lab = labels[r];
    if (lab == -100) { nll[r] = 0.f; valid[r] = 0.f; }
    else {
        nll[r] = logf(S) - logits[(size_t)r * CV + lab];
        valid[r] = 1.f;
    }
}

__global__ void loss_final_kernel(const float* __restrict__ nll,
                                  const float* __restrict__ valid,
                                  float* __restrict__ out)
{
    __shared__ float sm[8], sc[8];
    float s = 0.f, c = 0.f;
    for (int i = threadIdx.x; i < CBS; i += blockDim.x) { s += nll[i]; c += valid[i]; }
    for (int o = 16; o > 0; o >>= 1) {
        s += __shfl_xor_sync(0xffffffffu, s, o);
        c += __shfl_xor_sync(0xffffffffu, c, o);
    }
    if ((threadIdx.x & 31) == 0) { sm[threadIdx.x >> 5] = s; sc[threadIdx.x >> 5] = c; }
    __syncthreads();
    if (threadIdx.x == 0) {
        float ts = 0.f, tc = 0.f;
        for (int i = 0; i < 8; i++) { ts += sm[i]; tc += sc[i]; }
        out[0] = ts / fmaxf(tc, 1.f);
    }
}

// ---------------- host orchestration ----------------
extern "C" void kernel_launch(void* const* d_in, const int* in_sizes, int n_in,
                              void* d_out, int out_size)
{
    const int* ids    = (const int*)d_in[0];
    const int* labels = (const int*)d_in[1];
    const float* P[27];
    for (int i = 2; i < 27; i++) P[i] = (const float*)d_in[i];

    const float* emb[2]   = { P[2],  P[14] };
    const float* norm[2]  = { P[3],  P[15] };
    const float* inw[2]   = { P[4],  P[16] };
    const float* convw[2] = { P[5],  P[17] };
    const float* convb[2] = { P[6],  P[18] };
    const float* xpw[2]   = { P[7],  P[19] };
    const float* dtw[2]   = { P[8],  P[20] };
    const float* dtb[2]   = { P[9],  P[21] };
    const float* Alog[2]  = { P[10], P[22] };
    const float* Dp[2]    = { P[11], P[23] };
    const float* outw[2]  = { P[12], P[24] };
    const float* fnorm[2] = { P[13], P[25] };
    const float* lm_w     = P[26];

    static int smem_set = 0;
    if (!smem_set) {
        cudaFuncSetAttribute(gemm_tc, cudaFuncAttributeMaxDynamicSharedMemorySize, GEMM_SMEM);
        smem_set = 1;
    }

    float* arena = nullptr;
    cudaGetSymbolAddress((void**)&arena, g_arena);
    __half* planes = nullptr;
    cudaGetSymbolAddress((void**)&planes, g_planes);

    size_t fo = 0;
    auto fbump = [&](size_t n) { float* p = arena + fo; fo += n; return p; };
    size_t po = 0;
    auto pbump = [&](size_t n) { __half* p = planes + po; po += n; return p; };

    // weight hi planes (single plane per weight)
    __half* inwW  = pbump(2 * W_INW);
    __half* xpwW  = pbump(2 * W_XPW);
    __half* dtwW  = pbump(2 * W_DTW);
    __half* outwW = pbump(2 * W_OUTW);
    __half* lmW   = pbump(W_LM);

    // activation hi/lo planes
    __half* xnH  = pbump(2 * A_H);
    __half* xnL  = pbump(2 * A_H);
    __half* xcHp = pbump(2 * A_XC);
    __half* xcLp = pbump(2 * A_XC);
    __half* dbcHp = pbump(2 * A_DBC);
    __half* dbcLp = pbump(2 * A_DBC);
    __half* gHp = pbump(2 * A_XC);
    __half* gLp = pbump(2 * A_XC);
    __half* combH = pbump(A_COMB);
    __half* combL = pbump(A_COMB);

    float* hB   = fbump(2 * A_H);
    float* xzB  = fbump(2 * A_XZ);
    float* xcB  = fbump(2 * A_XC);
    float* dbcB = fbump(2 * A_DBC);
    float* dtB  = fbump(2 * A_XC);
    float* yB   = fbump(2 * A_XC);
    float* part = fbump(A_PART);
    float* Pb = fbump(2 * A_PL);
    float* Lb = fbump(2 * A_PL);
    float* Hs = fbump(2 * A_PL);
    float* nllb = fbump(CBS);
    float* valb = fbump(CBS);
    float* logits = (float*)d_out;

    SplitArgs sa;
    int si = 0;
    auto addseg = [&](const float* src, __half* h, size_t n) {
        sa.src[si] = (const float4*)src;
        sa.h2[si] = (__half2*)h;
        sa.n4[si] = n / 4;
        si++;
    };
    for (int d = 0; d < 2; d++) {
        addseg(inw[d],  inwW + d * W_INW,   W_INW);
        addseg(xpw[d],  xpwW + d * W_XPW,   W_XPW);
        addseg(dtw[d],  dtwW + d * W_DTW,   W_DTW);
        addseg(outw[d], outwW + d * W_OUTW, W_OUTW);
    }
    addseg(lm_w, lmW, W_LM);
    split_all_kernel<<<dim3(512, NSEG), 256>>>(sa);   // #1

    const int EL_THREADS = 256;
    int grid_hdm2 = (int)((2 * (size_t)CBS * CDM + EL_THREADS - 1) / EL_THREADS);
    int grid_hdi2 = (int)((2 * (size_t)CBS * CDI + EL_THREADS - 1) / EL_THREADS);
    int grid_scan2 = (2 * CB * CDI * NCH * 16 + 255) / 256;
    int grid_stitch2 = (2 * CB * CDI * 16 + 255) / 256;

    embed_kernel<<<grid_hdm2, EL_THREADS>>>(ids, emb[0], emb[1], hB);   // #2

    for (int l = 0; l < CL; l++) {
        size_t loI = (size_t)l * 2 * CDI * CDM;
        size_t loX = (size_t)l * CDBC * CDI;
        size_t loD = (size_t)l * CDI * CDR;
        size_t loO = (size_t)l * CDM * CDI;

        rms_kernel<<<2 * CBS, 256>>>(hB, norm[0] + (size_t)l * CDM, norm[1] + (size_t)l * CDM,
                                     xnH, xnL);                          // #3 (l=0)
        // xz = xn @ inw^T                                               // #4 (l=0) <- profiled
        gemm_tc<<<dim3(CBS / BM, (2 * CDI) / BN, 2), 256, GEMM_SMEM>>>(
            xnH, xnL, CDM, inwW + loI,
            xzB, CBS, 2 * CDI, CDM, nullptr, nullptr, 0, 0,
            nullptr, nullptr, nullptr,
            A_H, W_INW, A_XZ);
        conv_kernel<<<grid_hdi2, EL_THREADS>>>(
            xzB, convw[0] + (size_t)l * CDI * CKC, convw[1] + (size_t)l * CDI * CKC,
            convb[0] + (size_t)l * CDI, convb[1] + (size_t)l * CDI,
            xcB, xcHp, xcLp);
        // dbc = xc @ xpw^T
        gemm_tc<<<dim3(CBS / BM, 1, 2), 256, GEMM_SMEM>>>(
            xcHp, xcLp, CDI, xpwW + loX,
            dbcB, CBS, CDBC, CDI, nullptr, nullptr, 0, 0,
            dbcHp, dbcLp, nullptr,
            A_XC, W_XPW, A_DBC);
        // dt = softplus(dbc[:, :48] @ dtw^T + dtb)
        gemm_tc<<<dim3(CBS / BM, CDI / BN, 2), 256, GEMM_SMEM>>>(
            dbcHp, dbcLp, CDBC, dtwW + loD,
            dtB, CBS, CDI, CDR,
            dtb[0] + (size_t)l * CDI, dtb[1] + (size_t)l * CDI, 1, 0,
            nullptr, nullptr, nullptr,
            A_DBC, W_DTW, A_XC);
        scan_p1<<<grid_scan2, 256>>>(dtB, xcB, dbcB,
                                     Alog[0] + (size_t)l * CDI * CDS,
                                     Alog[1] + (size_t)l * CDI * CDS, Pb, Lb);
        scan_stitch<<<grid_stitch2, 256>>>(Pb, Lb, Hs);
        scan_p2<<<grid_scan2, 256>>>(dtB, xcB, dbcB,
                                     Alog[0] + (size_t)l * CDI * CDS,
                                     Alog[1] + (size_t)l * CDI * CDS, Hs, yB);
        gate_kernel<<<grid_hdi2, EL_THREADS>>>(
            yB, xcB, xzB, Dp[0] + (size_t)l * CDI, Dp[1] + (size_t)l * CDI,
            gHp, gLp);
        // h += g @ outw^T
        gemm_tc<<<dim3(CBS / BM, CDM / BN, 2), 256, GEMM_SMEM>>>(
            gHp, gLp, CDI, outwW + loO,
            hB, CBS, CDM, CDI, nullptr, nullptr, 0, 1,
            nullptr, nullptr, nullptr,
            A_XC, W_OUTW, A_H);
    }

    combined_kernel<<<CBS, 256>>>(hB, hB + A_H, fnorm[0], fnorm[1], combH, combL);

    // LM head (+ fused exp partials)
    gemm_tc<<<dim3(CBS / BM, CV / BN, 1), 256, GEMM_SMEM>>>(
        combH, combL, 2 * CDM, lmW,
        logits, CBS, CV, 2 * CDM, nullptr, nullptr, 0, 0,
        nullptr, nullptr, part,
        0, 0, 0);

    loss_sum_kernel<<<(CBS + 255) / 256, 256>>>(part, logits, labels, nllb, valb);
    loss_final_kernel<<<1, 256>>>(nllb, valb, logits + (out_size - 1));
}